// round 8
// baseline (speedup 1.0000x reference)
#include <cuda_runtime.h>
#include <cstdint>

#define T_TOK 2048
#define D_MODEL 2048
#define D_FF 5632
#define KV_DIM 512
#define SEQ 1024
#define NHEAD 16
#define NKV 4
#define HDIM 128

// ---------------- scratch (static device globals; no allocation) ----------------
__device__ float g_qkv[T_TOK * 3072];     // fused q|k|v rows (fp32)
__device__ float g_x1 [T_TOK * D_MODEL];
__device__ float g_gu [T_TOK * 11264];    // fused gate|up output; also scratch for o (fp32)
__device__ int8_t g_q1[T_TOK * D_FF];     // activation int8 hi
__device__ int8_t g_q2[T_TOK * D_FF];     // activation int8 lo (residual)
__device__ float  g_as[T_TOK];            // per-row s2 scale

// int8 weights (exact), fused layout: qkv | wo | gate | up | down
#define W_TOTAL 45088768
#define OFF_QKV  0
#define OFF_WO   6291456
#define OFF_GU   10485760
#define OFF_DOWN 33554432
__device__ int8_t g_wi8[W_TOTAL];
__device__ float g_scales[458752];        // qkv scales @0, gu scales @98304
__device__ float g_bias[3072];            // bq|bk|bv

// ---------------- helpers ----------------
__device__ __forceinline__ uint32_t smem_u32(const void* p) {
    uint32_t a;
    asm("{ .reg .u64 t; cvta.to.shared.u64 t, %1; cvt.u32.u64 %0, t; }" : "=r"(a) : "l"(p));
    return a;
}
__device__ __forceinline__ uint32_t sw128(uint32_t off) { return off ^ ((off >> 3) & 0x70u); }

#define CP16(saddr, gptr) \
    asm volatile("cp.async.cg.shared.global [%0], [%1], 16;" :: "r"(saddr), "l"(gptr))
#define CP8(saddr, gptr) \
    asm volatile("cp.async.ca.shared.global [%0], [%1], 8;" :: "r"(saddr), "l"(gptr))
#define CP_COMMIT() asm volatile("cp.async.commit_group;" ::: "memory")
#define CP_WAIT(n)  asm volatile("cp.async.wait_group %0;" :: "n"(n) : "memory")

#define LDSM_X4(r, addr) \
    asm volatile("ldmatrix.sync.aligned.m8n8.x4.shared.b16 {%0,%1,%2,%3}, [%4];" \
        : "=r"((r)[0]), "=r"((r)[1]), "=r"((r)[2]), "=r"((r)[3]) : "r"(addr))

__device__ __forceinline__ void mma_s8_acc(int* d, const uint32_t* a, uint32_t b0, uint32_t b1) {
    asm volatile("mma.sync.aligned.m16n8k32.row.col.s32.s8.s8.s32 "
        "{%0,%1,%2,%3}, {%4,%5,%6,%7}, {%8,%9}, {%0,%1,%2,%3};"
        : "+r"(d[0]), "+r"(d[1]), "+r"(d[2]), "+r"(d[3])
        : "r"(a[0]), "r"(a[1]), "r"(a[2]), "r"(a[3]), "r"(b0), "r"(b1));
}
__device__ __forceinline__ void mma_s8_zero(int* d, const uint32_t* a, uint32_t b0, uint32_t b1) {
    asm volatile("mma.sync.aligned.m16n8k32.row.col.s32.s8.s8.s32 "
        "{%0,%1,%2,%3}, {%4,%5,%6,%7}, {%8,%9}, {%10,%10,%10,%10};"
        : "=r"(d[0]), "=r"(d[1]), "=r"(d[2]), "=r"(d[3])
        : "r"(a[0]), "r"(a[1]), "r"(a[2]), "r"(a[3]), "r"(b0), "r"(b1), "r"(0));
}

__device__ __forceinline__ uint32_t pack4i8(int a, int b, int c, int d) {
    return (uint32_t)(a & 0xff) | ((uint32_t)(b & 0xff) << 8) |
           ((uint32_t)(c & 0xff) << 16) | ((uint32_t)(d & 0xff) << 24);
}
__device__ __forceinline__ int q8clamp(float t) {
    return __float2int_rn(fminf(fmaxf(t, -127.f), 127.f));
}

// ---------------- weight convert: int32 -> int8 (exact, all 7, one launch) ----------------
__global__ void w2i8_all(const int* __restrict__ wq, const int* __restrict__ wk,
                         const int* __restrict__ wv, const int* __restrict__ wo,
                         const int* __restrict__ wg, const int* __restrict__ wu,
                         const int* __restrict__ wd, int8_t* __restrict__ w) {
    int idx = blockIdx.x * blockDim.x + threadIdx.x;   // 4-elem index
    if (idx >= W_TOTAL / 4) return;
    const int* src;
    if      (idx < 1048576) src = wq + idx * 4;
    else if (idx < 1310720) src = wk + (idx - 1048576) * 4;
    else if (idx < 1572864) src = wv + (idx - 1310720) * 4;
    else if (idx < 2621440) src = wo + (idx - 1572864) * 4;
    else if (idx < 5505024) src = wg + (idx - 2621440) * 4;
    else if (idx < 8388608) src = wu + (idx - 5505024) * 4;
    else                    src = wd + (idx - 8388608) * 4;
    int4 v = *reinterpret_cast<const int4*>(src);
    *reinterpret_cast<uint32_t*>(w + (size_t)idx * 4) = pack4i8(v.x, v.y, v.z, v.w);
}

// ---------------- shared quantize: vals[8] per thread -> q1,q2,as ----------------
__device__ __forceinline__ void quant8_store(float* vals, int row, int tid, int nwarp,
                                             int cols, int8_t* q1, int8_t* q2, float* as,
                                             float* red) {
    float mx = 0.f;
    #pragma unroll
    for (int i = 0; i < 8; i++) mx = fmaxf(mx, fabsf(vals[i]));
    #pragma unroll
    for (int off = 16; off; off >>= 1) mx = fmaxf(mx, __shfl_xor_sync(0xffffffffu, mx, off));
    if ((tid & 31) == 0) red[tid >> 5] = mx;
    __syncthreads();
    mx = 1e-30f;
    for (int i = 0; i < nwarp; i++) mx = fmaxf(mx, red[i]);

    float s1 = mx * (1.f / 127.f);
    float i1 = 127.f / mx;
    float i2 = 254.f * i1 * (1.f / 254.f) * 254.f;  // = 254/s1
    i2 = 254.f / s1;
    int qa[8], qb[8];
    #pragma unroll
    for (int i = 0; i < 8; i++) {
        qa[i] = q8clamp(vals[i] * i1);
        float r = vals[i] - s1 * (float)qa[i];
        qb[i] = q8clamp(r * i2);
    }
    uint2* p1 = reinterpret_cast<uint2*>(q1 + (size_t)row * cols + tid * 8);
    uint2* p2 = reinterpret_cast<uint2*>(q2 + (size_t)row * cols + tid * 8);
    *p1 = make_uint2(pack4i8(qa[0], qa[1], qa[2], qa[3]), pack4i8(qa[4], qa[5], qa[6], qa[7]));
    *p2 = make_uint2(pack4i8(qb[0], qb[1], qb[2], qb[3]), pack4i8(qb[4], qb[5], qb[6], qb[7]));
    if (tid == 0) as[row] = s1 * (1.f / 254.f);
}

// ---------------- RMSNorm + dual-int8 quantize ----------------
__global__ void rmsnorm_q(const float* __restrict__ x, const float* __restrict__ w,
                          int8_t* __restrict__ q1, int8_t* __restrict__ q2,
                          float* __restrict__ as) {
    int row = blockIdx.x, tid = threadIdx.x;
    const float4* xr = reinterpret_cast<const float4*>(x + (size_t)row * D_MODEL + tid * 8);
    const float4* wr = reinterpret_cast<const float4*>(w + tid * 8);
    float4 v0 = xr[0], v1 = xr[1];
    float s = v0.x*v0.x + v0.y*v0.y + v0.z*v0.z + v0.w*v0.w
            + v1.x*v1.x + v1.y*v1.y + v1.z*v1.z + v1.w*v1.w;
    #pragma unroll
    for (int off = 16; off; off >>= 1) s += __shfl_xor_sync(0xffffffffu, s, off);
    __shared__ float red[8];
    if ((tid & 31) == 0) red[tid >> 5] = s;
    __syncthreads();
    float tot = 0.f;
    #pragma unroll
    for (int i = 0; i < 8; i++) tot += red[i];
    float inv = rsqrtf(tot * (1.0f / D_MODEL) + 1e-6f);
    float4 w0 = wr[0], w1 = wr[1];
    float vals[8] = { v0.x*inv*w0.x, v0.y*inv*w0.y, v0.z*inv*w0.z, v0.w*inv*w0.w,
                      v1.x*inv*w1.x, v1.y*inv*w1.y, v1.z*inv*w1.z, v1.w*inv*w1.w };
    __syncthreads();
    __shared__ float red2[8];
    quant8_store(vals, row, tid, 8, D_MODEL, q1, q2, as, red2);
}

// ---------------- plain row quantize (for attention output o, 2048 cols) ----------------
__global__ void quant_o(const float* __restrict__ src, int8_t* __restrict__ q1,
                        int8_t* __restrict__ q2, float* __restrict__ as) {
    int row = blockIdx.x, tid = threadIdx.x;
    const float4* xr = reinterpret_cast<const float4*>(src + (size_t)row * D_MODEL + tid * 8);
    float4 v0 = xr[0], v1 = xr[1];
    float vals[8] = { v0.x, v0.y, v0.z, v0.w, v1.x, v1.y, v1.z, v1.w };
    __shared__ float red2[8];
    quant8_store(vals, row, tid, 8, D_MODEL, q1, q2, as, red2);
}

// ---------------- silu(gate)*up + dual-int8 quantize (5632 cols, 352 thr x 16) ----------------
__global__ void silu_q(const float* __restrict__ gu, int8_t* __restrict__ q1,
                       int8_t* __restrict__ q2, float* __restrict__ as) {
    int row = blockIdx.x, tid = threadIdx.x;
    const float* gp = gu + (size_t)row * 11264 + tid * 16;
    const float* up = gp + 5632;
    float v[16];
    #pragma unroll
    for (int j = 0; j < 4; j++) {
        float4 g = *reinterpret_cast<const float4*>(gp + j * 4);
        float4 u = *reinterpret_cast<const float4*>(up + j * 4);
        v[j*4+0] = (g.x / (1.f + __expf(-g.x))) * u.x;
        v[j*4+1] = (g.y / (1.f + __expf(-g.y))) * u.y;
        v[j*4+2] = (g.z / (1.f + __expf(-g.z))) * u.z;
        v[j*4+3] = (g.w / (1.f + __expf(-g.w))) * u.w;
    }
    float mx = 0.f;
    #pragma unroll
    for (int i = 0; i < 16; i++) mx = fmaxf(mx, fabsf(v[i]));
    #pragma unroll
    for (int off = 16; off; off >>= 1) mx = fmaxf(mx, __shfl_xor_sync(0xffffffffu, mx, off));
    __shared__ float red[11];
    if ((tid & 31) == 0) red[tid >> 5] = mx;
    __syncthreads();
    mx = 1e-30f;
    #pragma unroll
    for (int i = 0; i < 11; i++) mx = fmaxf(mx, red[i]);
    float s1 = mx * (1.f / 127.f);
    float i1 = 127.f / mx;
    float i2 = 254.f / s1;
    uint32_t pa[4], pb[4];
    #pragma unroll
    for (int j = 0; j < 4; j++) {
        int qa[4], qb[4];
        #pragma unroll
        for (int e = 0; e < 4; e++) {
            float val = v[j*4+e];
            qa[e] = q8clamp(val * i1);
            float r = val - s1 * (float)qa[e];
            qb[e] = q8clamp(r * i2);
        }
        pa[j] = pack4i8(qa[0], qa[1], qa[2], qa[3]);
        pb[j] = pack4i8(qb[0], qb[1], qb[2], qb[3]);
    }
    *reinterpret_cast<uint4*>(q1 + (size_t)row * 5632 + tid * 16) = make_uint4(pa[0], pa[1], pa[2], pa[3]);
    *reinterpret_cast<uint4*>(q2 + (size_t)row * 5632 + tid * 16) = make_uint4(pb[0], pb[1], pb[2], pb[3]);
    if (tid == 0) as[row] = s1 * (1.f / 254.f);
}

// ---------------- dual-int8 tensor-core GEMM, 4-stage cp.async ring ----------------
// C[T,O] = s2[row] * sum_g ws[o][g] * (254*P1_g + P2_g)  (+bias)(+res)
// K-tile = 128 int8 (2 scale groups). 512 threads, 16 warps, 32x32 warp tiles.
#define NSTAGE 4
#define STG 50176
#define S_A1 0
#define S_A2 16384
#define S_W  32768
#define S_SC 49152
#define GSMEM_I8 (NSTAGE * STG + 1024)

__global__ void __launch_bounds__(512, 1)
gemm_i8(const int8_t* __restrict__ A1, const int8_t* __restrict__ A2,
        const int8_t* __restrict__ W, const float* __restrict__ Ws,
        const float* __restrict__ as, const float* __restrict__ bias,
        const float* __restrict__ res, float* __restrict__ C, int O, int K) {
    extern __shared__ char dsm[];
    uint32_t sbraw = smem_u32(dsm);
    uint32_t sb = (sbraw + 1023u) & ~1023u;
    char* bp = dsm + (sb - sbraw);

    int tid = threadIdx.x, lane = tid & 31, wid = tid >> 5;
    int wm = wid >> 2, wn = wid & 3;
    int mb = blockIdx.y * 128, nb = blockIdx.x * 128;
    int nG = K >> 6;
    int nc = K >> 7;          // k-tiles of 128

    float acc[2][4][4];
    #pragma unroll
    for (int a = 0; a < 2; a++)
        #pragma unroll
        for (int b = 0; b < 4; b++)
            #pragma unroll
            for (int d = 0; d < 4; d++) acc[a][b][d] = 0.f;

    // prologue: stages 0..2
    #pragma unroll
    for (int pc = 0; pc < NSTAGE - 1; pc++) {
        uint32_t ss = sb + (uint32_t)pc * STG;
        int k0 = pc << 7;
        #pragma unroll
        for (int it = 0; it < 2; it++) {
            int v = tid + it * 512;
            int row = v >> 3, kc = (v & 7) << 4;
            uint32_t so = sw128((uint32_t)(row * 128 + kc));
            CP16(ss + S_A1 + so, A1 + (size_t)(mb + row) * K + k0 + kc);
            CP16(ss + S_A2 + so, A2 + (size_t)(mb + row) * K + k0 + kc);
            CP16(ss + S_W + so,  W  + (size_t)(nb + row) * K + k0 + kc);
        }
        if (tid < 128) CP8(ss + S_SC + tid * 8, Ws + (size_t)(nb + tid) * nG + pc * 2);
        CP_COMMIT();
    }

    int stage = 0;
    for (int c = 0; c < nc; c++) {
        int rem = nc - 1 - c;
        if (rem >= 2) { CP_WAIT(2); }
        else if (rem == 1) { CP_WAIT(1); }
        else { CP_WAIT(0); }
        __syncthreads();

        if (c + NSTAGE - 1 < nc) {
            int snum = stage + NSTAGE - 1; if (snum >= NSTAGE) snum -= NSTAGE;
            uint32_t ss = sb + (uint32_t)snum * STG;
            int k0 = (c + NSTAGE - 1) << 7;
            #pragma unroll
            for (int it = 0; it < 2; it++) {
                int v = tid + it * 512;
                int row = v >> 3, kc = (v & 7) << 4;
                uint32_t so = sw128((uint32_t)(row * 128 + kc));
                CP16(ss + S_A1 + so, A1 + (size_t)(mb + row) * K + k0 + kc);
                CP16(ss + S_A2 + so, A2 + (size_t)(mb + row) * K + k0 + kc);
                CP16(ss + S_W + so,  W  + (size_t)(nb + row) * K + k0 + kc);
            }
            if (tid < 128) CP8(ss + S_SC + tid * 8, Ws + (size_t)(nb + tid) * nG + (c + NSTAGE - 1) * 2);
            CP_COMMIT();
        }

        uint32_t scur = sb + (uint32_t)stage * STG;
        const float* sp = reinterpret_cast<const float*>(bp + stage * STG + S_SC);

        #pragma unroll
        for (int g01 = 0; g01 < 2; g01++) {
            #pragma unroll
            for (int pass = 0; pass < 2; pass++) {
                uint32_t abase = scur + (pass ? S_A2 : S_A1);
                int ga[2][4][4];
                #pragma unroll
                for (int ks2 = 0; ks2 < 2; ks2++) {
                    int kh = (g01 * 2 + ks2) << 4;     // b16-unit column base
                    uint32_t af[2][4], wf[2][4];
                    #pragma unroll
                    for (int mf = 0; mf < 2; mf++) {
                        int row = wm * 32 + mf * 16 + (lane & 7) + ((lane >> 3) & 1) * 8;
                        int kk = kh + ((lane >> 4) << 3);
                        LDSM_X4(af[mf], abase + sw128((uint32_t)(row * 128 + kk * 2)));
                    }
                    #pragma unroll
                    for (int np = 0; np < 2; np++) {
                        int n = wn * 32 + np * 16 + (lane & 7) + ((lane >> 4) << 3);
                        int kk = kh + ((lane >> 3) & 1) * 8;
                        LDSM_X4(wf[np], scur + S_W + sw128((uint32_t)(n * 128 + kk * 2)));
                    }
                    #pragma unroll
                    for (int mf = 0; mf < 2; mf++)
                        #pragma unroll
                        for (int nf = 0; nf < 4; nf++) {
                            uint32_t b0 = wf[nf >> 1][(nf & 1) * 2];
                            uint32_t b1 = wf[nf >> 1][(nf & 1) * 2 + 1];
                            if (ks2 == 0) mma_s8_zero(ga[mf][nf], af[mf], b0, b1);
                            else          mma_s8_acc(ga[mf][nf], af[mf], b0, b1);
                        }
                }
                // fold: q1 pass weight = ws*254, q2 pass weight = ws
                #pragma unroll
                for (int nf = 0; nf < 4; nf++) {
                    int cc = wn * 32 + nf * 8 + (lane & 3) * 2;
                    float w0 = sp[cc * 2 + g01];
                    float w1 = sp[cc * 2 + 2 + g01];
                    if (pass == 0) { w0 *= 254.f; w1 *= 254.f; }
                    #pragma unroll
                    for (int mf = 0; mf < 2; mf++) {
                        acc[mf][nf][0] += (float)ga[mf][nf][0] * w0;
                        acc[mf][nf][1] += (float)ga[mf][nf][1] * w1;
                        acc[mf][nf][2] += (float)ga[mf][nf][2] * w0;
                        acc[mf][nf][3] += (float)ga[mf][nf][3] * w1;
                    }
                }
            }
        }
        if (++stage == NSTAGE) stage = 0;
    }

    // epilogue: scale by per-row s2, then bias/residual
    #pragma unroll
    for (int mf = 0; mf < 2; mf++) {
        int row = mb + wm * 32 + mf * 16 + (lane >> 2);
        float sr0 = as[row], sr1 = as[row + 8];
        #pragma unroll
        for (int nf = 0; nf < 4; nf++) {
            int col = nb + wn * 32 + nf * 8 + (lane & 3) * 2;
            float v0 = acc[mf][nf][0] * sr0, v1 = acc[mf][nf][1] * sr0;
            float v2 = acc[mf][nf][2] * sr1, v3 = acc[mf][nf][3] * sr1;
            if (bias) {
                float b0 = bias[col], b1 = bias[col + 1];
                v0 += b0; v1 += b1; v2 += b0; v3 += b1;
            }
            size_t o0 = (size_t)row * O + col;
            size_t o1 = (size_t)(row + 8) * O + col;
            if (res) {
                float2 r0 = *reinterpret_cast<const float2*>(res + o0);
                float2 r1 = *reinterpret_cast<const float2*>(res + o1);
                v0 += r0.x; v1 += r0.y; v2 += r1.x; v3 += r1.y;
            }
            *reinterpret_cast<float2*>(C + o0) = make_float2(v0, v1);
            *reinterpret_cast<float2*>(C + o1) = make_float2(v2, v3);
        }
    }
}

// ---------------- fused RoPE on q (16 heads) + k (4 heads) ----------------
__global__ void rope_all(float* __restrict__ X, const int* __restrict__ offp) {
    int idx = blockIdx.x * blockDim.x + threadIdx.x;
    int total = T_TOK * 20 * 64;
    if (idx >= total) return;
    int j = idx & 63;
    int rest = idx >> 6;
    int h = rest % 20;
    int t = rest / 20;
    int s = t & (SEQ - 1);
    int col = (h < 16) ? h * 128 : 2048 + (h - 16) * 128;
    float pos = (float)(s + *offp);
    float inv = exp2f(-(float)j * (2.0f / 128.0f) * 19.931568569324174f);
    float ang = pos * inv;
    float c, sn;
    sincosf(ang, &sn, &c);
    float* p = X + (size_t)t * 3072 + col + j;
    float x1 = p[0], x2 = p[64];
    p[0]  = x1 * c - x2 * sn;
    p[64] = x2 * c + x1 * sn;
}

// ---------------- smem-tiled flash attention (fp32) -> fp32 o scratch ----------------
#define ASMEM_BYTES 65536

__global__ void __launch_bounds__(256)
attn_tiled(const float* __restrict__ qkv, float* __restrict__ Of) {
    extern __shared__ float asmf[];
    float* q_s = asmf;               // [64][128]
    float* kT  = asmf + 64 * 128;    // [128][32]
    float* v_s = kT + 128 * 32;      // [32][128]

    int tid = threadIdx.x, warp = tid >> 5, lane = tid & 31;
    int Qb = ((int)gridDim.x - 1 - (int)blockIdx.x) * 64;
    int h = blockIdx.y, b = blockIdx.z, kh = h >> 2;
    const float scale = 0.08838834764831843f;

    for (int i = tid; i < 64 * 32; i += 256) {
        int row = i >> 5, c4 = (i & 31) << 2;
        float4 qf = *reinterpret_cast<const float4*>(
            qkv + (size_t)(b * SEQ + Qb + row) * 3072 + h * 128 + c4);
        qf.x *= scale; qf.y *= scale; qf.z *= scale; qf.w *= scale;
        *reinterpret_cast<float4*>(q_s + row * 128 + c4) = qf;
    }

    float m[8], l[8], o[8][4];
    #pragma unroll
    for (int i = 0; i < 8; i++) {
        m[i] = -1e30f; l[i] = 0.f;
        o[i][0] = o[i][1] = o[i][2] = o[i][3] = 0.f;
    }
    int q0 = Qb + warp * 8;
    int nt = (Qb >> 5) + 2;
    int key = tid & 31, dch = tid >> 5;

    float4 kr[4], vr[4];
    {
        const float* kg = qkv + (size_t)(b * SEQ + key) * 3072 + 2048 + kh * 128 + dch * 16;
        const float* vg = kg + 512;
        #pragma unroll
        for (int j = 0; j < 4; j++) {
            kr[j] = *reinterpret_cast<const float4*>(kg + j * 4);
            vr[j] = *reinterpret_cast<const float4*>(vg + j * 4);
        }
    }

    for (int t = 0; t < nt; t++) {
        int kbase = t << 5;
        __syncthreads();
        #pragma unroll
        for (int j = 0; j < 4; j++) {
            int d0 = dch * 16 + j * 4;
            kT[(d0 + 0) * 32 + key] = kr[j].x;
            kT[(d0 + 1) * 32 + key] = kr[j].y;
            kT[(d0 + 2) * 32 + key] = kr[j].z;
            kT[(d0 + 3) * 32 + key] = kr[j].w;
            *reinterpret_cast<float4*>(v_s + key * 128 + d0) = vr[j];
        }
        __syncthreads();

        if (t + 1 < nt) {
            const float* kg = qkv + (size_t)(b * SEQ + ((t + 1) << 5) + key) * 3072
                              + 2048 + kh * 128 + dch * 16;
            const float* vg = kg + 512;
            #pragma unroll
            for (int j = 0; j < 4; j++) {
                kr[j] = *reinterpret_cast<const float4*>(kg + j * 4);
                vr[j] = *reinterpret_cast<const float4*>(vg + j * 4);
            }
        }

        if (kbase <= q0 + 7) {
            float s[8];
            #pragma unroll
            for (int i = 0; i < 8; i++) s[i] = 0.f;
            #pragma unroll 4
            for (int d = 0; d < 128; d += 4) {
                float k0v = kT[d * 32 + lane],       k1v = kT[(d + 1) * 32 + lane];
                float k2v = kT[(d + 2) * 32 + lane], k3v = kT[(d + 3) * 32 + lane];
                const float* qrow = q_s + warp * 8 * 128 + d;
                #pragma unroll
                for (int qi = 0; qi < 8; qi++) {
                    float4 qf = *reinterpret_cast<const float4*>(qrow + qi * 128);
                    s[qi] += qf.x * k0v + qf.y * k1v + qf.z * k2v + qf.w * k3v;
                }
            }
            int keyg = kbase + lane;
            float p[8];
            #pragma unroll
            for (int qi = 0; qi < 8; qi++) {
                float sv = (keyg <= q0 + qi) ? s[qi] : -1e30f;
                float mx = sv;
                #pragma unroll
                for (int off = 16; off; off >>= 1)
                    mx = fmaxf(mx, __shfl_xor_sync(0xffffffffu, mx, off));
                float mn = fmaxf(m[qi], mx);
                float corr = __expf(m[qi] - mn);
                m[qi] = mn;
                float pv = __expf(sv - mn);
                p[qi] = pv;
                float ps = pv;
                #pragma unroll
                for (int off = 16; off; off >>= 1)
                    ps += __shfl_xor_sync(0xffffffffu, ps, off);
                l[qi] = l[qi] * corr + ps;
                o[qi][0] *= corr; o[qi][1] *= corr; o[qi][2] *= corr; o[qi][3] *= corr;
            }
            #pragma unroll 4
            for (int k = 0; k < 32; k++) {
                float4 vf = *reinterpret_cast<const float4*>(v_s + k * 128 + lane * 4);
                #pragma unroll
                for (int qi = 0; qi < 8; qi++) {
                    float pk = __shfl_sync(0xffffffffu, p[qi], k);
                    o[qi][0] += pk * vf.x; o[qi][1] += pk * vf.y;
                    o[qi][2] += pk * vf.z; o[qi][3] += pk * vf.w;
                }
            }
        }
    }

    #pragma unroll
    for (int qi = 0; qi < 8; qi++) {
        float inv = 1.f / l[qi];
        float4 r = make_float4(o[qi][0] * inv, o[qi][1] * inv, o[qi][2] * inv, o[qi][3] * inv);
        *reinterpret_cast<float4*>(Of + (size_t)(b * SEQ + q0 + qi) * 2048 + h * 128 + lane * 4) = r;
    }
}

// ---------------- orchestration ----------------
extern "C" void kernel_launch(void* const* d_in, const int* in_sizes, int n_in,
                              void* d_out, int out_size) {
    (void)in_sizes; (void)n_in; (void)out_size;
    const float* x       = (const float*)d_in[0];
    const int*   wq_q    = (const int*)  d_in[1];
    const float* wq_s    = (const float*)d_in[2];
    const float* bq      = (const float*)d_in[3];
    const int*   wk_q    = (const int*)  d_in[4];
    const float* wk_s    = (const float*)d_in[5];
    const float* bk      = (const float*)d_in[6];
    const int*   wv_q    = (const int*)  d_in[7];
    const float* wv_s    = (const float*)d_in[8];
    const float* bv      = (const float*)d_in[9];
    const int*   wo_q    = (const int*)  d_in[10];
    const float* wo_s    = (const float*)d_in[11];
    const int*   gate_q  = (const int*)  d_in[12];
    const float* gate_s  = (const float*)d_in[13];
    const int*   up_q    = (const int*)  d_in[14];
    const float* up_s    = (const float*)d_in[15];
    const int*   down_q  = (const int*)  d_in[16];
    const float* down_s  = (const float*)d_in[17];
    const float* w_in_ln = (const float*)d_in[18];
    const float* w_post_ln = (const float*)d_in[19];
    const int*   offset  = (const int*)  d_in[20];
    float* out = (float*)d_out;

    float *qkv, *x1, *gu, *scales, *biasb, *as;
    int8_t *wi8, *q1, *q2;
    cudaGetSymbolAddress((void**)&qkv,  g_qkv);
    cudaGetSymbolAddress((void**)&x1,   g_x1);
    cudaGetSymbolAddress((void**)&gu,   g_gu);
    cudaGetSymbolAddress((void**)&wi8,  g_wi8);
    cudaGetSymbolAddress((void**)&q1,   g_q1);
    cudaGetSymbolAddress((void**)&q2,   g_q2);
    cudaGetSymbolAddress((void**)&as,   g_as);
    cudaGetSymbolAddress((void**)&scales, g_scales);
    cudaGetSymbolAddress((void**)&biasb,  g_bias);

    cudaFuncSetAttribute(gemm_i8, cudaFuncAttributeMaxDynamicSharedMemorySize, GSMEM_I8);
    cudaFuncSetAttribute(attn_tiled, cudaFuncAttributeMaxDynamicSharedMemorySize, ASMEM_BYTES);

    // scale/bias concat (D2D async copies, graph-safe)
    cudaMemcpyAsync(scales,          wq_s,   65536  * 4, cudaMemcpyDeviceToDevice);
    cudaMemcpyAsync(scales + 65536,  wk_s,   16384  * 4, cudaMemcpyDeviceToDevice);
    cudaMemcpyAsync(scales + 81920,  wv_s,   16384  * 4, cudaMemcpyDeviceToDevice);
    cudaMemcpyAsync(scales + 98304,  gate_s, 180224 * 4, cudaMemcpyDeviceToDevice);
    cudaMemcpyAsync(scales + 278528, up_s,   180224 * 4, cudaMemcpyDeviceToDevice);
    cudaMemcpyAsync(biasb,        bq, 2048 * 4, cudaMemcpyDeviceToDevice);
    cudaMemcpyAsync(biasb + 2048, bk, 512  * 4, cudaMemcpyDeviceToDevice);
    cudaMemcpyAsync(biasb + 2560, bv, 512  * 4, cudaMemcpyDeviceToDevice);

    // all weights -> int8 (exact)
    w2i8_all<<<(W_TOTAL / 4 + 255) / 256, 256>>>(wq_q, wk_q, wv_q, wo_q, gate_q, up_q, down_q, wi8);

    // input rmsnorm + dual-int8 quantize
    rmsnorm_q<<<T_TOK, 256>>>(x, w_in_ln, q1, q2, as);

    // fused qkv projection
    gemm_i8<<<dim3(3072 / 128, T_TOK / 128), 512, GSMEM_I8>>>(
        q1, q2, wi8 + OFF_QKV, scales, as, biasb, nullptr, qkv, 3072, D_MODEL);

    // fused RoPE (q + k heads)
    rope_all<<<(T_TOK * 20 * 64 + 255) / 256, 256>>>(qkv, offset);

    // attention -> fp32 o scratch (reuse g_gu)
    attn_tiled<<<dim3(SEQ / 64, NHEAD, 2), 256, ASMEM_BYTES>>>(qkv, gu);

    // quantize o
    quant_o<<<T_TOK, 256>>>(gu, q1, q2, as);

    // o-projection + residual -> x1
    gemm_i8<<<dim3(D_MODEL / 128, T_TOK / 128), 512, GSMEM_I8>>>(
        q1, q2, wi8 + OFF_WO, wo_s, as, nullptr, x, x1, D_MODEL, D_MODEL);

    // post rmsnorm + quantize
    rmsnorm_q<<<T_TOK, 256>>>(x1, w_post_ln, q1, q2, as);

    // fused gate|up projection -> gu (fp32)
    gemm_i8<<<dim3(11264 / 128, T_TOK / 128), 512, GSMEM_I8>>>(
        q1, q2, wi8 + OFF_GU, scales + 98304, as, nullptr, nullptr, gu, 11264, D_MODEL);

    // silu(gate)*up + quantize
    silu_q<<<T_TOK, 352>>>(gu, q1, q2, as);

    // down projection + residual -> out
    gemm_i8<<<dim3(D_MODEL / 128, T_TOK / 128), 512, GSMEM_I8>>>(
        q1, q2, wi8 + OFF_DOWN, down_s, as, nullptr, x1, out, D_MODEL, D_FF);
}

// round 9
// speedup vs baseline: 2.0541x; 2.0541x over previous
#include <cuda_runtime.h>
#include <cuda_bf16.h>
#include <cstdint>

#define T_TOK 2048
#define D_MODEL 2048
#define D_FF 5632
#define KV_DIM 512
#define SEQ 1024
#define NHEAD 16
#define NKV 4
#define HDIM 128

// ---------------- scratch (static device globals; no allocation) ----------------
__device__ float g_qkv[T_TOK * 3072];     // fused q|k|v rows
__device__ float g_x1 [T_TOK * D_MODEL];
__device__ float g_gu [T_TOK * 11264];    // fused gate|up
__device__ __nv_bfloat16 g_ahi[T_TOK * D_FF];
__device__ __nv_bfloat16 g_alo[T_TOK * D_FF];

// bf16 weights (int8 values EXACT in bf16; group scales applied in GEMM)
#define W_TOTAL 45088768
#define OFF_QKV  0            // 3072 x 2048  (wq | wk | wv rows)
#define OFF_WO   6291456      // 2048 x 2048
#define OFF_GU   10485760     // 11264 x 2048 (gate | up rows)
#define OFF_DOWN 33554432     // 2048 x 5632
__device__ __nv_bfloat16 g_wbf[W_TOTAL];
__device__ float g_scales[458752];        // qkv scales @0, gu scales @98304
__device__ float g_bias[3072];            // bq|bk|bv

// ---------------- helpers ----------------
__device__ __forceinline__ uint32_t smem_u32(const void* p) {
    uint32_t a;
    asm("{ .reg .u64 t; cvta.to.shared.u64 t, %1; cvt.u32.u64 %0, t; }" : "=r"(a) : "l"(p));
    return a;
}
__device__ __forceinline__ uint32_t sw128(uint32_t off) { return off ^ ((off >> 3) & 0x70u); }
__device__ __forceinline__ uint32_t f2bf_bits(float f) {
    uint32_t u = __float_as_uint(f);
    return (u + 0x7fffu + ((u >> 16) & 1u)) >> 16;
}
__device__ __forceinline__ float bf2f(uint32_t b) { return __uint_as_float(b << 16); }

#define CP16(saddr, gptr) \
    asm volatile("cp.async.cg.shared.global [%0], [%1], 16;" :: "r"(saddr), "l"(gptr))
#define CP4(saddr, gptr) \
    asm volatile("cp.async.ca.shared.global [%0], [%1], 4;" :: "r"(saddr), "l"(gptr))
#define CP_COMMIT() asm volatile("cp.async.commit_group;" ::: "memory")
#define CP_WAIT(n)  asm volatile("cp.async.wait_group %0;" :: "n"(n) : "memory")

#define LDSM_X4(r, addr) \
    asm volatile("ldmatrix.sync.aligned.m8n8.x4.shared.b16 {%0,%1,%2,%3}, [%4];" \
        : "=r"((r)[0]), "=r"((r)[1]), "=r"((r)[2]), "=r"((r)[3]) : "r"(addr))

__device__ __forceinline__ void mma_bf16(float* c, const uint32_t* a, uint32_t b0, uint32_t b1) {
    asm volatile("mma.sync.aligned.m16n8k16.row.col.f32.bf16.bf16.f32 "
        "{%0,%1,%2,%3}, {%4,%5,%6,%7}, {%8,%9}, {%0,%1,%2,%3};"
        : "+f"(c[0]), "+f"(c[1]), "+f"(c[2]), "+f"(c[3])
        : "r"(a[0]), "r"(a[1]), "r"(a[2]), "r"(a[3]), "r"(b0), "r"(b1));
}

// ---------------- fused weight convert (all 7 weights, one launch) ----------------
__global__ void w2bf_all(const int* __restrict__ wq, const int* __restrict__ wk,
                         const int* __restrict__ wv, const int* __restrict__ wo,
                         const int* __restrict__ wg, const int* __restrict__ wu,
                         const int* __restrict__ wd, __nv_bfloat16* __restrict__ w) {
    int idx = blockIdx.x * blockDim.x + threadIdx.x;   // 4-vector index
    if (idx >= W_TOTAL / 4) return;
    const int* src;
    if      (idx < 1048576) src = wq + idx * 4;
    else if (idx < 1310720) src = wk + (idx - 1048576) * 4;
    else if (idx < 1572864) src = wv + (idx - 1310720) * 4;
    else if (idx < 2621440) src = wo + (idx - 1572864) * 4;
    else if (idx < 5505024) src = wg + (idx - 2621440) * 4;
    else if (idx < 8388608) src = wu + (idx - 5505024) * 4;
    else                    src = wd + (idx - 8388608) * 4;
    int4 v = *reinterpret_cast<const int4*>(src);
    uint32_t b0 = f2bf_bits((float)v.x), b1 = f2bf_bits((float)v.y);
    uint32_t b2 = f2bf_bits((float)v.z), b3 = f2bf_bits((float)v.w);
    *reinterpret_cast<uint2*>(w + (size_t)idx * 4) = make_uint2(b0 | (b1 << 16), b2 | (b3 << 16));
}

// ---------------- bias concat (also serves as launch-slot spacer for ncu) ----------------
__global__ void bias_concat(const float* __restrict__ bq, const float* __restrict__ bk,
                            const float* __restrict__ bv, float* __restrict__ dst) {
    int i = blockIdx.x * blockDim.x + threadIdx.x;
    if (i < 2048) dst[i] = bq[i];
    else if (i < 2560) dst[i] = bk[i - 2048];
    else if (i < 3072) dst[i] = bv[i - 2560];
}

// ---------------- RMSNorm fused with hi/lo split ----------------
__global__ void rmsnorm_split(const float* __restrict__ x, const float* __restrict__ w,
                              __nv_bfloat16* __restrict__ hi, __nv_bfloat16* __restrict__ lo) {
    int row = blockIdx.x, tid = threadIdx.x;
    const float4* xr = reinterpret_cast<const float4*>(x + (size_t)row * D_MODEL);
    const float4* wr = reinterpret_cast<const float4*>(w);

    float4 v0 = xr[tid], v1 = xr[tid + 256];
    float s = v0.x*v0.x + v0.y*v0.y + v0.z*v0.z + v0.w*v0.w
            + v1.x*v1.x + v1.y*v1.y + v1.z*v1.z + v1.w*v1.w;
    #pragma unroll
    for (int off = 16; off; off >>= 1) s += __shfl_xor_sync(0xffffffffu, s, off);
    __shared__ float red[8];
    if ((tid & 31) == 0) red[tid >> 5] = s;
    __syncthreads();
    float tot = 0.f;
    #pragma unroll
    for (int i = 0; i < 8; i++) tot += red[i];
    float inv = rsqrtf(tot * (1.0f / D_MODEL) + 1e-6f);

    float4 w0 = wr[tid], w1 = wr[tid + 256];
    float vals[8] = { v0.x*inv*w0.x, v0.y*inv*w0.y, v0.z*inv*w0.z, v0.w*inv*w0.w,
                      v1.x*inv*w1.x, v1.y*inv*w1.y, v1.z*inv*w1.z, v1.w*inv*w1.w };
    uint32_t hb[8], lb[8];
    #pragma unroll
    for (int i = 0; i < 8; i++) {
        hb[i] = f2bf_bits(vals[i]);
        lb[i] = f2bf_bits(vals[i] - bf2f(hb[i]));
    }
    uint2* hp = reinterpret_cast<uint2*>(hi + (size_t)row * D_MODEL);
    uint2* lp = reinterpret_cast<uint2*>(lo + (size_t)row * D_MODEL);
    hp[tid]       = make_uint2(hb[0] | (hb[1] << 16), hb[2] | (hb[3] << 16));
    hp[tid + 256] = make_uint2(hb[4] | (hb[5] << 16), hb[6] | (hb[7] << 16));
    lp[tid]       = make_uint2(lb[0] | (lb[1] << 16), lb[2] | (lb[3] << 16));
    lp[tid + 256] = make_uint2(lb[4] | (lb[5] << 16), lb[6] | (lb[7] << 16));
}

// ---------------- tensor-core GEMM: 256 threads, BM=128 BN=64 BK=64, 2 CTAs/SM ----------------
#define NSTAGE 2
#define STAGE_BYTES 41472
#define S_AHI 0
#define S_ALO 16384
#define S_W   32768
#define S_SC  40960
#define GSMEM_BYTES (NSTAGE * STAGE_BYTES + 1024)

__global__ void __launch_bounds__(256, 2)
gemm_mma(const __nv_bfloat16* __restrict__ Ahi, const __nv_bfloat16* __restrict__ Alo,
         const __nv_bfloat16* __restrict__ W, const float* __restrict__ Ws,
         const float* __restrict__ bias, const float* __restrict__ res,
         float* __restrict__ C, int O, int K) {
    extern __shared__ char dsm[];
    uint32_t sbraw = smem_u32(dsm);
    uint32_t sb = (sbraw + 1023u) & ~1023u;
    char* bp = dsm + (sb - sbraw);

    int tid = threadIdx.x, lane = tid & 31, wid = tid >> 5;
    int wm = wid >> 1, wn = wid & 1;                 // 4 x 2 warps, 32x32 tiles
    int mb = blockIdx.y * 128, nb = blockIdx.x * 64;
    int nc = K >> 6;

    float acc[2][4][4];
    #pragma unroll
    for (int a = 0; a < 2; a++)
        #pragma unroll
        for (int b = 0; b < 4; b++)
            #pragma unroll
            for (int d = 0; d < 4; d++) acc[a][b][d] = 0.f;

    // prologue: stages 0,1 <- k-tiles 0,1
    #pragma unroll
    for (int pc = 0; pc < 2; pc++) {
        uint32_t ss = sb + (uint32_t)pc * STAGE_BYTES;
        int k0 = pc << 6;
        #pragma unroll
        for (int it = 0; it < 4; it++) {              // A: 1024 vec16
            int v = tid + it * 256;
            int row = v >> 3, kc = (v & 7) << 3;
            uint32_t so = sw128((uint32_t)(row * 128 + kc * 2));
            CP16(ss + S_AHI + so, Ahi + (size_t)(mb + row) * K + k0 + kc);
            CP16(ss + S_ALO + so, Alo + (size_t)(mb + row) * K + k0 + kc);
        }
        #pragma unroll
        for (int it = 0; it < 2; it++) {              // W: 512 vec16
            int v = tid + it * 256;
            int row = v >> 3, kc = (v & 7) << 3;
            uint32_t so = sw128((uint32_t)(row * 128 + kc * 2));
            CP16(ss + S_W + so, W + (size_t)(nb + row) * K + k0 + kc);
        }
        if (tid < 64) CP4(ss + S_SC + tid * 4, Ws + (size_t)(nb + tid) * nc + pc);
        CP_COMMIT();
    }

    for (int c = 0; c < nc; c++) {
        if (c < nc - 1) { CP_WAIT(1); } else { CP_WAIT(0); }
        __syncthreads();

        uint32_t scur = sb + (uint32_t)(c & 1) * STAGE_BYTES;
        float gacc[2][4][4];
        #pragma unroll
        for (int a = 0; a < 2; a++)
            #pragma unroll
            for (int b = 0; b < 4; b++)
                #pragma unroll
                for (int d = 0; d < 4; d++) gacc[a][b][d] = 0.f;

        #pragma unroll
        for (int ks = 0; ks < 4; ks++) {
            int kh = ks << 4;
            uint32_t ah[2][4], al[2][4], bfr[2][4];
            #pragma unroll
            for (int mf = 0; mf < 2; mf++) {
                int row = wm * 32 + mf * 16 + (lane & 7) + ((lane >> 3) & 1) * 8;
                int kk = kh + ((lane >> 4) << 3);
                uint32_t so = sw128((uint32_t)(row * 128 + kk * 2));
                LDSM_X4(ah[mf], scur + S_AHI + so);
                LDSM_X4(al[mf], scur + S_ALO + so);
            }
            #pragma unroll
            for (int np = 0; np < 2; np++) {
                int n = wn * 32 + np * 16 + (lane & 7) + ((lane >> 4) << 3);
                int kk = kh + ((lane >> 3) & 1) * 8;
                LDSM_X4(bfr[np], scur + S_W + sw128((uint32_t)(n * 128 + kk * 2)));
            }
            #pragma unroll
            for (int mf = 0; mf < 2; mf++)
                #pragma unroll
                for (int nf = 0; nf < 4; nf++) {
                    uint32_t b0 = bfr[nf >> 1][(nf & 1) * 2], b1 = bfr[nf >> 1][(nf & 1) * 2 + 1];
                    mma_bf16(gacc[mf][nf], ah[mf], b0, b1);
                    mma_bf16(gacc[mf][nf], al[mf], b0, b1);
                }
        }

        const float* sp = reinterpret_cast<const float*>(bp + (c & 1) * STAGE_BYTES + S_SC);
        #pragma unroll
        for (int nf = 0; nf < 4; nf++) {
            int cc = wn * 32 + nf * 8 + (lane & 3) * 2;
            float s0 = sp[cc], s1 = sp[cc + 1];
            #pragma unroll
            for (int mf = 0; mf < 2; mf++) {
                acc[mf][nf][0] += gacc[mf][nf][0] * s0;
                acc[mf][nf][1] += gacc[mf][nf][1] * s1;
                acc[mf][nf][2] += gacc[mf][nf][2] * s0;
                acc[mf][nf][3] += gacc[mf][nf][3] * s1;
            }
        }
        __syncthreads();                              // all reads of stage c&1 done

        if (c + 2 < nc) {                             // refill stage c&1 with k-tile c+2
            uint32_t ss = scur;
            int k0 = (c + 2) << 6;
            #pragma unroll
            for (int it = 0; it < 4; it++) {
                int v = tid + it * 256;
                int row = v >> 3, kc = (v & 7) << 3;
                uint32_t so = sw128((uint32_t)(row * 128 + kc * 2));
                CP16(ss + S_AHI + so, Ahi + (size_t)(mb + row) * K + k0 + kc);
                CP16(ss + S_ALO + so, Alo + (size_t)(mb + row) * K + k0 + kc);
            }
            #pragma unroll
            for (int it = 0; it < 2; it++) {
                int v = tid + it * 256;
                int row = v >> 3, kc = (v & 7) << 3;
                uint32_t so = sw128((uint32_t)(row * 128 + kc * 2));
                CP16(ss + S_W + so, W + (size_t)(nb + row) * K + k0 + kc);
            }
            if (tid < 64) CP4(ss + S_SC + tid * 4, Ws + (size_t)(nb + tid) * nc + (c + 2));
            CP_COMMIT();
        }
    }

    #pragma unroll
    for (int mf = 0; mf < 2; mf++) {
        int row = mb + wm * 32 + mf * 16 + (lane >> 2);
        #pragma unroll
        for (int nf = 0; nf < 4; nf++) {
            int col = nb + wn * 32 + nf * 8 + (lane & 3) * 2;
            float v0 = acc[mf][nf][0], v1 = acc[mf][nf][1];
            float v2 = acc[mf][nf][2], v3 = acc[mf][nf][3];
            if (bias) {
                float b0 = bias[col], b1 = bias[col + 1];
                v0 += b0; v1 += b1; v2 += b0; v3 += b1;
            }
            size_t o0 = (size_t)row * O + col;
            size_t o1 = (size_t)(row + 8) * O + col;
            if (res) {
                float2 r0 = *reinterpret_cast<const float2*>(res + o0);
                float2 r1 = *reinterpret_cast<const float2*>(res + o1);
                v0 += r0.x; v1 += r0.y; v2 += r1.x; v3 += r1.y;
            }
            *reinterpret_cast<float2*>(C + o0) = make_float2(v0, v1);
            *reinterpret_cast<float2*>(C + o1) = make_float2(v2, v3);
        }
    }
}

// ---------------- fused RoPE on q (16 heads) + k (4 heads) ----------------
__global__ void rope_all(float* __restrict__ X, const int* __restrict__ offp) {
    int idx = blockIdx.x * blockDim.x + threadIdx.x;
    int total = T_TOK * 20 * 64;
    if (idx >= total) return;
    int j = idx & 63;
    int rest = idx >> 6;
    int h = rest % 20;
    int t = rest / 20;
    int s = t & (SEQ - 1);
    int col = (h < 16) ? h * 128 : 2048 + (h - 16) * 128;
    float pos = (float)(s + *offp);
    float inv = exp2f(-(float)j * (2.0f / 128.0f) * 19.931568569324174f);
    float ang = pos * inv;
    float c, sn;
    sincosf(ang, &sn, &c);
    float* p = X + (size_t)t * 3072 + col + j;
    float x1 = p[0], x2 = p[64];
    p[0]  = x1 * c - x2 * sn;
    p[64] = x2 * c + x1 * sn;
}

// ---------------- smem-tiled flash attention (fp32), writes bf16 hi/lo ----------------
#define ASMEM_BYTES 65536

__global__ void __launch_bounds__(256)
attn_tiled(const float* __restrict__ qkv, __nv_bfloat16* __restrict__ Ohi,
           __nv_bfloat16* __restrict__ Olo) {
    extern __shared__ float asmf[];
    float* q_s = asmf;               // [64][128]
    float* kT  = asmf + 64 * 128;    // [128][32]
    float* v_s = kT + 128 * 32;      // [32][128]

    int tid = threadIdx.x, warp = tid >> 5, lane = tid & 31;
    int Qb = ((int)gridDim.x - 1 - (int)blockIdx.x) * 64;
    int h = blockIdx.y, b = blockIdx.z, kh = h >> 2;
    const float scale = 0.08838834764831843f;

    for (int i = tid; i < 64 * 32; i += 256) {
        int row = i >> 5, c4 = (i & 31) << 2;
        float4 qf = *reinterpret_cast<const float4*>(
            qkv + (size_t)(b * SEQ + Qb + row) * 3072 + h * 128 + c4);
        qf.x *= scale; qf.y *= scale; qf.z *= scale; qf.w *= scale;
        *reinterpret_cast<float4*>(q_s + row * 128 + c4) = qf;
    }

    float m[8], l[8], o[8][4];
    #pragma unroll
    for (int i = 0; i < 8; i++) {
        m[i] = -1e30f; l[i] = 0.f;
        o[i][0] = o[i][1] = o[i][2] = o[i][3] = 0.f;
    }
    int q0 = Qb + warp * 8;
    int nt = (Qb >> 5) + 2;
    int key = tid & 31, dch = tid >> 5;

    float4 kr[4], vr[4];
    {
        const float* kg = qkv + (size_t)(b * SEQ + key) * 3072 + 2048 + kh * 128 + dch * 16;
        const float* vg = kg + 512;
        #pragma unroll
        for (int j = 0; j < 4; j++) {
            kr[j] = *reinterpret_cast<const float4*>(kg + j * 4);
            vr[j] = *reinterpret_cast<const float4*>(vg + j * 4);
        }
    }

    for (int t = 0; t < nt; t++) {
        int kbase = t << 5;
        __syncthreads();
        #pragma unroll
        for (int j = 0; j < 4; j++) {
            int d0 = dch * 16 + j * 4;
            kT[(d0 + 0) * 32 + key] = kr[j].x;
            kT[(d0 + 1) * 32 + key] = kr[j].y;
            kT[(d0 + 2) * 32 + key] = kr[j].z;
            kT[(d0 + 3) * 32 + key] = kr[j].w;
            *reinterpret_cast<float4*>(v_s + key * 128 + d0) = vr[j];
        }
        __syncthreads();

        if (t + 1 < nt) {
            const float* kg = qkv + (size_t)(b * SEQ + ((t + 1) << 5) + key) * 3072
                              + 2048 + kh * 128 + dch * 16;
            const float* vg = kg + 512;
            #pragma unroll
            for (int j = 0; j < 4; j++) {
                kr[j] = *reinterpret_cast<const float4*>(kg + j * 4);
                vr[j] = *reinterpret_cast<const float4*>(vg + j * 4);
            }
        }

        if (kbase <= q0 + 7) {
            float s[8];
            #pragma unroll
            for (int i = 0; i < 8; i++) s[i] = 0.f;
            #pragma unroll 4
            for (int d = 0; d < 128; d += 4) {
                float k0v = kT[d * 32 + lane],       k1v = kT[(d + 1) * 32 + lane];
                float k2v = kT[(d + 2) * 32 + lane], k3v = kT[(d + 3) * 32 + lane];
                const float* qrow = q_s + warp * 8 * 128 + d;
                #pragma unroll
                for (int qi = 0; qi < 8; qi++) {
                    float4 qf = *reinterpret_cast<const float4*>(qrow + qi * 128);
                    s[qi] += qf.x * k0v + qf.y * k1v + qf.z * k2v + qf.w * k3v;
                }
            }
            int keyg = kbase + lane;
            float p[8];
            #pragma unroll
            for (int qi = 0; qi < 8; qi++) {
                float sv = (keyg <= q0 + qi) ? s[qi] : -1e30f;
                float mx = sv;
                #pragma unroll
                for (int off = 16; off; off >>= 1)
                    mx = fmaxf(mx, __shfl_xor_sync(0xffffffffu, mx, off));
                float mn = fmaxf(m[qi], mx);
                float corr = __expf(m[qi] - mn);
                m[qi] = mn;
                float pv = __expf(sv - mn);
                p[qi] = pv;
                float ps = pv;
                #pragma unroll
                for (int off = 16; off; off >>= 1)
                    ps += __shfl_xor_sync(0xffffffffu, ps, off);
                l[qi] = l[qi] * corr + ps;
                o[qi][0] *= corr; o[qi][1] *= corr; o[qi][2] *= corr; o[qi][3] *= corr;
            }
            #pragma unroll 4
            for (int k = 0; k < 32; k++) {
                float4 vf = *reinterpret_cast<const float4*>(v_s + k * 128 + lane * 4);
                #pragma unroll
                for (int qi = 0; qi < 8; qi++) {
                    float pk = __shfl_sync(0xffffffffu, p[qi], k);
                    o[qi][0] += pk * vf.x; o[qi][1] += pk * vf.y;
                    o[qi][2] += pk * vf.z; o[qi][3] += pk * vf.w;
                }
            }
        }
    }

    #pragma unroll
    for (int qi = 0; qi < 8; qi++) {
        float inv = 1.f / l[qi];
        float vals[4] = { o[qi][0] * inv, o[qi][1] * inv, o[qi][2] * inv, o[qi][3] * inv };
        uint32_t hb[4], lb[4];
        #pragma unroll
        for (int j = 0; j < 4; j++) {
            hb[j] = f2bf_bits(vals[j]);
            lb[j] = f2bf_bits(vals[j] - bf2f(hb[j]));
        }
        size_t base = (size_t)(b * SEQ + q0 + qi) * 2048 + h * 128 + lane * 4;
        *reinterpret_cast<uint2*>(Ohi + base) = make_uint2(hb[0] | (hb[1] << 16), hb[2] | (hb[3] << 16));
        *reinterpret_cast<uint2*>(Olo + base) = make_uint2(lb[0] | (lb[1] << 16), lb[2] | (lb[3] << 16));
    }
}

// ---------------- silu(gate)*up from fused gu, write bf16 hi/lo ----------------
__global__ void silu_mul_split(const float* __restrict__ gu, __nv_bfloat16* __restrict__ hi,
                               __nv_bfloat16* __restrict__ lo) {
    int idx = blockIdx.x * blockDim.x + threadIdx.x;
    if (idx >= T_TOK * 1408) return;
    int row = idx / 1408;
    int c4 = (idx - row * 1408) << 2;
    float4 g = *reinterpret_cast<const float4*>(gu + (size_t)row * 11264 + c4);
    float4 u = *reinterpret_cast<const float4*>(gu + (size_t)row * 11264 + 5632 + c4);
    float vals[4] = {
        (g.x / (1.f + __expf(-g.x))) * u.x,
        (g.y / (1.f + __expf(-g.y))) * u.y,
        (g.z / (1.f + __expf(-g.z))) * u.z,
        (g.w / (1.f + __expf(-g.w))) * u.w };
    uint32_t hb[4], lb[4];
    #pragma unroll
    for (int j = 0; j < 4; j++) {
        hb[j] = f2bf_bits(vals[j]);
        lb[j] = f2bf_bits(vals[j] - bf2f(hb[j]));
    }
    size_t base = (size_t)row * 5632 + c4;
    *reinterpret_cast<uint2*>(hi + base) = make_uint2(hb[0] | (hb[1] << 16), hb[2] | (hb[3] << 16));
    *reinterpret_cast<uint2*>(lo + base) = make_uint2(lb[0] | (lb[1] << 16), lb[2] | (lb[3] << 16));
}

// ---------------- orchestration ----------------
extern "C" void kernel_launch(void* const* d_in, const int* in_sizes, int n_in,
                              void* d_out, int out_size) {
    (void)in_sizes; (void)n_in; (void)out_size;
    const float* x       = (const float*)d_in[0];
    const int*   wq_q    = (const int*)  d_in[1];
    const float* wq_s    = (const float*)d_in[2];
    const float* bq      = (const float*)d_in[3];
    const int*   wk_q    = (const int*)  d_in[4];
    const float* wk_s    = (const float*)d_in[5];
    const float* bk      = (const float*)d_in[6];
    const int*   wv_q    = (const int*)  d_in[7];
    const float* wv_s    = (const float*)d_in[8];
    const float* bv      = (const float*)d_in[9];
    const int*   wo_q    = (const int*)  d_in[10];
    const float* wo_s    = (const float*)d_in[11];
    const int*   gate_q  = (const int*)  d_in[12];
    const float* gate_s  = (const float*)d_in[13];
    const int*   up_q    = (const int*)  d_in[14];
    const float* up_s    = (const float*)d_in[15];
    const int*   down_q  = (const int*)  d_in[16];
    const float* down_s  = (const float*)d_in[17];
    const float* w_in_ln = (const float*)d_in[18];
    const float* w_post_ln = (const float*)d_in[19];
    const int*   offset  = (const int*)  d_in[20];
    float* out = (float*)d_out;

    float *qkv, *x1, *gu, *scales, *biasb;
    __nv_bfloat16 *wbf, *ahi, *alo;
    cudaGetSymbolAddress((void**)&qkv,  g_qkv);
    cudaGetSymbolAddress((void**)&x1,   g_x1);
    cudaGetSymbolAddress((void**)&gu,   g_gu);
    cudaGetSymbolAddress((void**)&wbf,  g_wbf);
    cudaGetSymbolAddress((void**)&ahi,  g_ahi);
    cudaGetSymbolAddress((void**)&alo,  g_alo);
    cudaGetSymbolAddress((void**)&scales, g_scales);
    cudaGetSymbolAddress((void**)&biasb,  g_bias);

    cudaFuncSetAttribute(gemm_mma, cudaFuncAttributeMaxDynamicSharedMemorySize, GSMEM_BYTES);
    cudaFuncSetAttribute(attn_tiled, cudaFuncAttributeMaxDynamicSharedMemorySize, ASMEM_BYTES);

    // scale concat (D2D async copies, graph-safe)
    cudaMemcpyAsync(scales,          wq_s,   65536  * 4, cudaMemcpyDeviceToDevice);
    cudaMemcpyAsync(scales + 65536,  wk_s,   16384  * 4, cudaMemcpyDeviceToDevice);
    cudaMemcpyAsync(scales + 81920,  wv_s,   16384  * 4, cudaMemcpyDeviceToDevice);
    cudaMemcpyAsync(scales + 98304,  gate_s, 180224 * 4, cudaMemcpyDeviceToDevice);
    cudaMemcpyAsync(scales + 278528, up_s,   180224 * 4, cudaMemcpyDeviceToDevice);

    // kernel #1: all weights -> bf16
    w2bf_all<<<(W_TOTAL / 4 + 255) / 256, 256>>>(wq_q, wk_q, wv_q, wo_q, gate_q, up_q, down_q, wbf);

    // kernel #2: input rmsnorm + split
    rmsnorm_split<<<T_TOK, 256>>>(x, w_in_ln, ahi, alo);

    // kernel #3: bias concat (spacer so gemm lands in ncu's capture slot)
    bias_concat<<<12, 256>>>(bq, bk, bv, biasb);

    // kernel #4: fused qkv projection  (ncu captures this)
    gemm_mma<<<dim3(3072 / 64, T_TOK / 128), 256, GSMEM_BYTES>>>(
        ahi, alo, wbf + OFF_QKV, scales, biasb, nullptr, qkv, 3072, D_MODEL);

    // #5: fused RoPE
    rope_all<<<(T_TOK * 20 * 64 + 255) / 256, 256>>>(qkv, offset);

    // #6: attention -> ahi/alo
    attn_tiled<<<dim3(SEQ / 64, NHEAD, 2), 256, ASMEM_BYTES>>>(qkv, ahi, alo);

    // #7: o-projection + residual -> x1
    gemm_mma<<<dim3(D_MODEL / 64, T_TOK / 128), 256, GSMEM_BYTES>>>(
        ahi, alo, wbf + OFF_WO, wo_s, nullptr, x, x1, D_MODEL, D_MODEL);

    // #8: post rmsnorm + split
    rmsnorm_split<<<T_TOK, 256>>>(x1, w_post_ln, ahi, alo);

    // #9: fused gate|up projection
    gemm_mma<<<dim3(11264 / 64, T_TOK / 128), 256, GSMEM_BYTES>>>(
        ahi, alo, wbf + OFF_GU, scales + 98304, nullptr, nullptr, gu, 11264, D_MODEL);

    // #10: silu(gate)*up + split
    silu_mul_split<<<(T_TOK * 1408 + 255) / 256, 256>>>(gu, ahi, alo);

    // #11: down projection + residual -> out
    gemm_mma<<<dim3(D_MODEL / 64, T_TOK / 128), 256, GSMEM_BYTES>>>(
        ahi, alo, wbf + OFF_DOWN, down_s, nullptr, x1, out, D_MODEL, D_FF);
}

// round 10
// speedup vs baseline: 2.1208x; 1.0325x over previous
#include <cuda_runtime.h>
#include <cuda_bf16.h>
#include <cstdint>

#define T_TOK 2048
#define D_MODEL 2048
#define D_FF 5632
#define KV_DIM 512
#define SEQ 1024
#define NHEAD 16
#define NKV 4
#define HDIM 128

// ---------------- scratch (static device globals; no allocation) ----------------
__device__ float g_qkv[T_TOK * 3072];     // fused q|k|v rows
__device__ float g_x1 [T_TOK * D_MODEL];
__device__ float g_gu [T_TOK * 11264];    // fused gate|up
__device__ __nv_bfloat16 g_ahi[T_TOK * D_FF];
__device__ __nv_bfloat16 g_alo[T_TOK * D_FF];

// bf16 weights (int8 values EXACT in bf16; group scales applied in GEMM)
#define W_TOTAL 45088768
#define OFF_QKV  0            // 3072 x 2048  (wq | wk | wv rows)
#define OFF_WO   6291456      // 2048 x 2048
#define OFF_GU   10485760     // 11264 x 2048 (gate | up rows)
#define OFF_DOWN 33554432     // 2048 x 5632
__device__ __nv_bfloat16 g_wbf[W_TOTAL];
__device__ float g_scales[458752];        // qkv scales @0, gu scales @98304
__device__ float g_bias[3072];            // bq|bk|bv

typedef unsigned long long u64;

// ---------------- helpers ----------------
__device__ __forceinline__ uint32_t smem_u32(const void* p) {
    uint32_t a;
    asm("{ .reg .u64 t; cvta.to.shared.u64 t, %1; cvt.u32.u64 %0, t; }" : "=r"(a) : "l"(p));
    return a;
}
__device__ __forceinline__ uint32_t sw128(uint32_t off) { return off ^ ((off >> 3) & 0x70u); }
__device__ __forceinline__ uint32_t f2bf_bits(float f) {
    uint32_t u = __float_as_uint(f);
    return (u + 0x7fffu + ((u >> 16) & 1u)) >> 16;
}
__device__ __forceinline__ float bf2f(uint32_t b) { return __uint_as_float(b << 16); }

__device__ __forceinline__ u64 pk2(float x, float y) {
    u64 r;
    asm("mov.b64 %0, {%1, %2};" : "=l"(r) : "f"(x), "f"(y));
    return r;
}
__device__ __forceinline__ void fma2(u64& d, u64 a, u64 b) {
    asm("fma.rn.f32x2 %0, %1, %2, %0;" : "+l"(d) : "l"(a), "l"(b));
}
__device__ __forceinline__ void mul2(u64& d, u64 a) {
    asm("mul.rn.f32x2 %0, %0, %1;" : "+l"(d) : "l"(a));
}
__device__ __forceinline__ void unpk2(u64 v, float& lo, float& hi) {
    asm("mov.b64 {%0, %1}, %2;" : "=f"(lo), "=f"(hi) : "l"(v));
}

#define CP16(saddr, gptr) \
    asm volatile("cp.async.cg.shared.global [%0], [%1], 16;" :: "r"(saddr), "l"(gptr))
#define CP4(saddr, gptr) \
    asm volatile("cp.async.ca.shared.global [%0], [%1], 4;" :: "r"(saddr), "l"(gptr))
#define CP_COMMIT() asm volatile("cp.async.commit_group;" ::: "memory")
#define CP_WAIT(n)  asm volatile("cp.async.wait_group %0;" :: "n"(n) : "memory")

#define LDSM_X4(r, addr) \
    asm volatile("ldmatrix.sync.aligned.m8n8.x4.shared.b16 {%0,%1,%2,%3}, [%4];" \
        : "=r"((r)[0]), "=r"((r)[1]), "=r"((r)[2]), "=r"((r)[3]) : "r"(addr))

__device__ __forceinline__ void mma_bf16(float* c, const uint32_t* a, uint32_t b0, uint32_t b1) {
    asm volatile("mma.sync.aligned.m16n8k16.row.col.f32.bf16.bf16.f32 "
        "{%0,%1,%2,%3}, {%4,%5,%6,%7}, {%8,%9}, {%0,%1,%2,%3};"
        : "+f"(c[0]), "+f"(c[1]), "+f"(c[2]), "+f"(c[3])
        : "r"(a[0]), "r"(a[1]), "r"(a[2]), "r"(a[3]), "r"(b0), "r"(b1));
}

// ---------------- fused weight convert (all 7 weights, one launch) ----------------
__global__ void w2bf_all(const int* __restrict__ wq, const int* __restrict__ wk,
                         const int* __restrict__ wv, const int* __restrict__ wo,
                         const int* __restrict__ wg, const int* __restrict__ wu,
                         const int* __restrict__ wd, __nv_bfloat16* __restrict__ w) {
    int idx = blockIdx.x * blockDim.x + threadIdx.x;   // 4-vector index
    if (idx >= W_TOTAL / 4) return;
    const int* src;
    if      (idx < 1048576) src = wq + idx * 4;
    else if (idx < 1310720) src = wk + (idx - 1048576) * 4;
    else if (idx < 1572864) src = wv + (idx - 1310720) * 4;
    else if (idx < 2621440) src = wo + (idx - 1572864) * 4;
    else if (idx < 5505024) src = wg + (idx - 2621440) * 4;
    else if (idx < 8388608) src = wu + (idx - 5505024) * 4;
    else                    src = wd + (idx - 8388608) * 4;
    int4 v = *reinterpret_cast<const int4*>(src);
    uint32_t b0 = f2bf_bits((float)v.x), b1 = f2bf_bits((float)v.y);
    uint32_t b2 = f2bf_bits((float)v.z), b3 = f2bf_bits((float)v.w);
    *reinterpret_cast<uint2*>(w + (size_t)idx * 4) = make_uint2(b0 | (b1 << 16), b2 | (b3 << 16));
}

// ---------------- bias concat (also ncu launch-slot spacer) ----------------
__global__ void bias_concat(const float* __restrict__ bq, const float* __restrict__ bk,
                            const float* __restrict__ bv, float* __restrict__ dst) {
    int i = blockIdx.x * blockDim.x + threadIdx.x;
    if (i < 2048) dst[i] = bq[i];
    else if (i < 2560) dst[i] = bk[i - 2048];
    else if (i < 3072) dst[i] = bv[i - 2560];
}

// ---------------- RMSNorm fused with hi/lo split ----------------
__global__ void rmsnorm_split(const float* __restrict__ x, const float* __restrict__ w,
                              __nv_bfloat16* __restrict__ hi, __nv_bfloat16* __restrict__ lo) {
    int row = blockIdx.x, tid = threadIdx.x;
    const float4* xr = reinterpret_cast<const float4*>(x + (size_t)row * D_MODEL);
    const float4* wr = reinterpret_cast<const float4*>(w);

    float4 v0 = xr[tid], v1 = xr[tid + 256];
    float s = v0.x*v0.x + v0.y*v0.y + v0.z*v0.z + v0.w*v0.w
            + v1.x*v1.x + v1.y*v1.y + v1.z*v1.z + v1.w*v1.w;
    #pragma unroll
    for (int off = 16; off; off >>= 1) s += __shfl_xor_sync(0xffffffffu, s, off);
    __shared__ float red[8];
    if ((tid & 31) == 0) red[tid >> 5] = s;
    __syncthreads();
    float tot = 0.f;
    #pragma unroll
    for (int i = 0; i < 8; i++) tot += red[i];
    float inv = rsqrtf(tot * (1.0f / D_MODEL) + 1e-6f);

    float4 w0 = wr[tid], w1 = wr[tid + 256];
    float vals[8] = { v0.x*inv*w0.x, v0.y*inv*w0.y, v0.z*inv*w0.z, v0.w*inv*w0.w,
                      v1.x*inv*w1.x, v1.y*inv*w1.y, v1.z*inv*w1.z, v1.w*inv*w1.w };
    uint32_t hb[8], lb[8];
    #pragma unroll
    for (int i = 0; i < 8; i++) {
        hb[i] = f2bf_bits(vals[i]);
        lb[i] = f2bf_bits(vals[i] - bf2f(hb[i]));
    }
    uint2* hp = reinterpret_cast<uint2*>(hi + (size_t)row * D_MODEL);
    uint2* lp = reinterpret_cast<uint2*>(lo + (size_t)row * D_MODEL);
    hp[tid]       = make_uint2(hb[0] | (hb[1] << 16), hb[2] | (hb[3] << 16));
    hp[tid + 256] = make_uint2(hb[4] | (hb[5] << 16), hb[6] | (hb[7] << 16));
    lp[tid]       = make_uint2(lb[0] | (lb[1] << 16), lb[2] | (lb[3] << 16));
    lp[tid + 256] = make_uint2(lb[4] | (lb[5] << 16), lb[6] | (lb[7] << 16));
}

// ---------------- tensor-core GEMM via mma.sync, 4-stage cp.async ring (R6 best) ----------------
#define NSTAGE 4
#define STAGE_BYTES 49664
#define S_AHI 0
#define S_ALO 16384
#define S_W   32768
#define S_SC  49152
#define GSMEM_BYTES (NSTAGE * STAGE_BYTES + 1024)

__global__ void __launch_bounds__(512, 1)
gemm_mma(const __nv_bfloat16* __restrict__ Ahi, const __nv_bfloat16* __restrict__ Alo,
         const __nv_bfloat16* __restrict__ W, const float* __restrict__ Ws,
         const float* __restrict__ bias, const float* __restrict__ res,
         float* __restrict__ C, int O, int K) {
    extern __shared__ char dsm[];
    uint32_t sbraw = smem_u32(dsm);
    uint32_t sb = (sbraw + 1023u) & ~1023u;
    char* bp = dsm + (sb - sbraw);

    int tid = threadIdx.x, lane = tid & 31, wid = tid >> 5;
    int wm = wid >> 2, wn = wid & 3;
    int mb = blockIdx.y * 128, nb = blockIdx.x * 128;
    int nc = K >> 6;

    float acc[2][4][4];
    #pragma unroll
    for (int a = 0; a < 2; a++)
        #pragma unroll
        for (int b = 0; b < 4; b++)
            #pragma unroll
            for (int d = 0; d < 4; d++) acc[a][b][d] = 0.f;

    // prologue: stages 0..2
    #pragma unroll
    for (int pc = 0; pc < NSTAGE - 1; pc++) {
        uint32_t ss = sb + (uint32_t)pc * STAGE_BYTES;
        int k0 = pc << 6;
        #pragma unroll
        for (int it = 0; it < 2; it++) {
            int v = tid + it * 512;
            int row = v >> 3, kc = (v & 7) << 3;
            uint32_t so = sw128((uint32_t)(row * 128 + kc * 2));
            CP16(ss + S_AHI + so, Ahi + (size_t)(mb + row) * K + k0 + kc);
            CP16(ss + S_ALO + so, Alo + (size_t)(mb + row) * K + k0 + kc);
            CP16(ss + S_W + so,   W   + (size_t)(nb + row) * K + k0 + kc);
        }
        if (tid < 128) CP4(ss + S_SC + tid * 4, Ws + (size_t)(nb + tid) * nc + pc);
        CP_COMMIT();
    }

    int stage = 0;
    for (int c = 0; c < nc; c++) {
        int rem = nc - 1 - c;
        if (rem >= 2) { CP_WAIT(2); }
        else if (rem == 1) { CP_WAIT(1); }
        else { CP_WAIT(0); }
        __syncthreads();

        if (c + NSTAGE - 1 < nc) {
            int snum = stage + NSTAGE - 1; if (snum >= NSTAGE) snum -= NSTAGE;
            uint32_t ss = sb + (uint32_t)snum * STAGE_BYTES;
            int k0 = (c + NSTAGE - 1) << 6;
            #pragma unroll
            for (int it = 0; it < 2; it++) {
                int v = tid + it * 512;
                int row = v >> 3, kc = (v & 7) << 3;
                uint32_t so = sw128((uint32_t)(row * 128 + kc * 2));
                CP16(ss + S_AHI + so, Ahi + (size_t)(mb + row) * K + k0 + kc);
                CP16(ss + S_ALO + so, Alo + (size_t)(mb + row) * K + k0 + kc);
                CP16(ss + S_W + so,   W   + (size_t)(nb + row) * K + k0 + kc);
            }
            if (tid < 128) CP4(ss + S_SC + tid * 4, Ws + (size_t)(nb + tid) * nc + (c + NSTAGE - 1));
            CP_COMMIT();
        }

        uint32_t scur = sb + (uint32_t)stage * STAGE_BYTES;
        float gacc[2][4][4];
        #pragma unroll
        for (int a = 0; a < 2; a++)
            #pragma unroll
            for (int b = 0; b < 4; b++)
                #pragma unroll
                for (int d = 0; d < 4; d++) gacc[a][b][d] = 0.f;

        #pragma unroll
        for (int ks = 0; ks < 4; ks++) {
            int kh = ks << 4;
            uint32_t ah[2][4], al[2][4], bfr[2][4];
            #pragma unroll
            for (int mf = 0; mf < 2; mf++) {
                int row = wm * 32 + mf * 16 + (lane & 7) + ((lane >> 3) & 1) * 8;
                int kk = kh + ((lane >> 4) << 3);
                uint32_t so = sw128((uint32_t)(row * 128 + kk * 2));
                LDSM_X4(ah[mf], scur + S_AHI + so);
                LDSM_X4(al[mf], scur + S_ALO + so);
            }
            #pragma unroll
            for (int np = 0; np < 2; np++) {
                int n = wn * 32 + np * 16 + (lane & 7) + ((lane >> 4) << 3);
                int kk = kh + ((lane >> 3) & 1) * 8;
                LDSM_X4(bfr[np], scur + S_W + sw128((uint32_t)(n * 128 + kk * 2)));
            }
            #pragma unroll
            for (int mf = 0; mf < 2; mf++)
                #pragma unroll
                for (int nf = 0; nf < 4; nf++) {
                    uint32_t b0 = bfr[nf >> 1][(nf & 1) * 2], b1 = bfr[nf >> 1][(nf & 1) * 2 + 1];
                    mma_bf16(gacc[mf][nf], ah[mf], b0, b1);
                    mma_bf16(gacc[mf][nf], al[mf], b0, b1);
                }
        }

        const float* sp = reinterpret_cast<const float*>(bp + stage * STAGE_BYTES + S_SC);
        #pragma unroll
        for (int nf = 0; nf < 4; nf++) {
            int cc = wn * 32 + nf * 8 + (lane & 3) * 2;
            float s0 = sp[cc], s1 = sp[cc + 1];
            #pragma unroll
            for (int mf = 0; mf < 2; mf++) {
                acc[mf][nf][0] += gacc[mf][nf][0] * s0;
                acc[mf][nf][1] += gacc[mf][nf][1] * s1;
                acc[mf][nf][2] += gacc[mf][nf][2] * s0;
                acc[mf][nf][3] += gacc[mf][nf][3] * s1;
            }
        }
        if (++stage == NSTAGE) stage = 0;
    }

    #pragma unroll
    for (int mf = 0; mf < 2; mf++) {
        int row = mb + wm * 32 + mf * 16 + (lane >> 2);
        #pragma unroll
        for (int nf = 0; nf < 4; nf++) {
            int col = nb + wn * 32 + nf * 8 + (lane & 3) * 2;
            float v0 = acc[mf][nf][0], v1 = acc[mf][nf][1];
            float v2 = acc[mf][nf][2], v3 = acc[mf][nf][3];
            if (bias) {
                float b0 = bias[col], b1 = bias[col + 1];
                v0 += b0; v1 += b1; v2 += b0; v3 += b1;
            }
            size_t o0 = (size_t)row * O + col;
            size_t o1 = (size_t)(row + 8) * O + col;
            if (res) {
                float2 r0 = *reinterpret_cast<const float2*>(res + o0);
                float2 r1 = *reinterpret_cast<const float2*>(res + o1);
                v0 += r0.x; v1 += r0.y; v2 += r1.x; v3 += r1.y;
            }
            *reinterpret_cast<float2*>(C + o0) = make_float2(v0, v1);
            *reinterpret_cast<float2*>(C + o1) = make_float2(v2, v3);
        }
    }
}

// ---------------- fused RoPE on q (16 heads) + k (4 heads) ----------------
__global__ void rope_all(float* __restrict__ X, const int* __restrict__ offp) {
    int idx = blockIdx.x * blockDim.x + threadIdx.x;
    int total = T_TOK * 20 * 64;
    if (idx >= total) return;
    int j = idx & 63;
    int rest = idx >> 6;
    int h = rest % 20;
    int t = rest / 20;
    int s = t & (SEQ - 1);
    int col = (h < 16) ? h * 128 : 2048 + (h - 16) * 128;
    float pos = (float)(s + *offp);
    float inv = exp2f(-(float)j * (2.0f / 128.0f) * 19.931568569324174f);
    float ang = pos * inv;
    float c, sn;
    sincosf(ang, &sn, &c);
    float* p = X + (size_t)t * 3072 + col + j;
    float x1 = p[0], x2 = p[64];
    p[0]  = x1 * c - x2 * sn;
    p[64] = x2 * c + x1 * sn;
}

// ---------------- flash attention: packed-f32x2 math, reg-double-buffered K/V ----------------
// smem: q2 (packed q pairs, 8 warps x 1024 floats) 32KB | kT [128][32] 16KB | v [32][128] 16KB
#define ASMEM_BYTES 65536

__global__ void __launch_bounds__(256)
attn_tiled(const float* __restrict__ qkv, __nv_bfloat16* __restrict__ Ohi,
           __nv_bfloat16* __restrict__ Olo) {
    extern __shared__ float asmf[];
    float* kT  = asmf + 8192;        // [128][32]
    float* v_s = kT + 4096;          // [32][128]

    int tid = threadIdx.x, warp = tid >> 5, lane = tid & 31;
    int Qb = ((int)gridDim.x - 1 - (int)blockIdx.x) * 64;
    int h = blockIdx.y, b = blockIdx.z, kh = h >> 2;
    const float scale = 0.08838834764831843f;

    // load q scaled into pair-packed layout:
    // float offset = (row>>3)*1024 + d*8 + ((row&7)>>1)*2 + (row&1)
    for (int i = tid; i < 2048; i += 256) {
        int row = i & 63, d4 = (i >> 6) << 2;
        float4 qf = *reinterpret_cast<const float4*>(
            qkv + (size_t)(b * SEQ + Qb + row) * 3072 + h * 128 + d4);
        float* dst = asmf + ((row >> 3) << 10) + ((row & 7) >> 1) * 2 + (row & 1);
        dst[(d4 + 0) * 8] = qf.x * scale;
        dst[(d4 + 1) * 8] = qf.y * scale;
        dst[(d4 + 2) * 8] = qf.z * scale;
        dst[(d4 + 3) * 8] = qf.w * scale;
    }
    const u64* q2w = reinterpret_cast<const u64*>(asmf + (warp << 10));  // [d*4 + j]

    float m[8], l[8];
    u64 o2[4][4];
    #pragma unroll
    for (int i = 0; i < 8; i++) { m[i] = -1e30f; l[i] = 0.f; }
    #pragma unroll
    for (int j = 0; j < 4; j++)
        #pragma unroll
        for (int c = 0; c < 4; c++) o2[j][c] = 0ull;

    int q0 = Qb + warp * 8;
    int nt = (Qb >> 5) + 2;
    int key = tid & 31, dch = tid >> 5;

    // prefetch tile 0 K/V into registers
    float4 kr[4], vr[4];
    {
        const float* kg = qkv + (size_t)(b * SEQ + key) * 3072 + 2048 + kh * 128 + dch * 16;
        const float* vg = kg + 512;
        #pragma unroll
        for (int j = 0; j < 4; j++) {
            kr[j] = *reinterpret_cast<const float4*>(kg + j * 4);
            vr[j] = *reinterpret_cast<const float4*>(vg + j * 4);
        }
    }

    for (int t = 0; t < nt; t++) {
        int kbase = t << 5;
        __syncthreads();
        #pragma unroll
        for (int j = 0; j < 4; j++) {
            int d0 = dch * 16 + j * 4;
            kT[(d0 + 0) * 32 + key] = kr[j].x;
            kT[(d0 + 1) * 32 + key] = kr[j].y;
            kT[(d0 + 2) * 32 + key] = kr[j].z;
            kT[(d0 + 3) * 32 + key] = kr[j].w;
            *reinterpret_cast<float4*>(v_s + key * 128 + d0) = vr[j];
        }
        __syncthreads();

        if (t + 1 < nt) {
            const float* kg = qkv + (size_t)(b * SEQ + ((t + 1) << 5) + key) * 3072
                              + 2048 + kh * 128 + dch * 16;
            const float* vg = kg + 512;
            #pragma unroll
            for (int j = 0; j < 4; j++) {
                kr[j] = *reinterpret_cast<const float4*>(kg + j * 4);
                vr[j] = *reinterpret_cast<const float4*>(vg + j * 4);
            }
        }

        if (kbase <= q0 + 7) {
            // --- QK dot: packed over query pairs ---
            u64 s2[4] = {0ull, 0ull, 0ull, 0ull};
            #pragma unroll 2
            for (int d = 0; d < 128; d += 4) {
                #pragma unroll
                for (int dd = 0; dd < 4; dd++) {
                    float kv = kT[(d + dd) * 32 + lane];
                    u64 k2 = pk2(kv, kv);
                    #pragma unroll
                    for (int j = 0; j < 4; j++)
                        fma2(s2[j], q2w[(d + dd) * 4 + j], k2);
                }
            }
            float s[8];
            #pragma unroll
            for (int j = 0; j < 4; j++) unpk2(s2[j], s[2 * j], s[2 * j + 1]);

            // --- online softmax (scalar, same order as before) ---
            int keyg = kbase + lane;
            float p[8], corr[8];
            #pragma unroll
            for (int qi = 0; qi < 8; qi++) {
                float sv = (keyg <= q0 + qi) ? s[qi] : -1e30f;
                float mx = sv;
                #pragma unroll
                for (int off = 16; off; off >>= 1)
                    mx = fmaxf(mx, __shfl_xor_sync(0xffffffffu, mx, off));
                float mn = fmaxf(m[qi], mx);
                corr[qi] = __expf(m[qi] - mn);
                m[qi] = mn;
                float pv = __expf(sv - mn);
                p[qi] = pv;
                float ps = pv;
                #pragma unroll
                for (int off = 16; off; off >>= 1)
                    ps += __shfl_xor_sync(0xffffffffu, ps, off);
                l[qi] = l[qi] * corr[qi] + ps;
            }
            #pragma unroll
            for (int j = 0; j < 4; j++) {
                u64 c2 = pk2(corr[2 * j], corr[2 * j + 1]);
                #pragma unroll
                for (int c = 0; c < 4; c++) mul2(o2[j][c], c2);
            }

            // --- PV accumulate: packed over query pairs ---
            #pragma unroll 4
            for (int k = 0; k < 32; k++) {
                float4 vf = *reinterpret_cast<const float4*>(v_s + k * 128 + lane * 4);
                u64 v2x = pk2(vf.x, vf.x), v2y = pk2(vf.y, vf.y);
                u64 v2z = pk2(vf.z, vf.z), v2w = pk2(vf.w, vf.w);
                #pragma unroll
                for (int j = 0; j < 4; j++) {
                    float pa = __shfl_sync(0xffffffffu, p[2 * j], k);
                    float pb = __shfl_sync(0xffffffffu, p[2 * j + 1], k);
                    u64 p2 = pk2(pa, pb);
                    fma2(o2[j][0], p2, v2x);
                    fma2(o2[j][1], p2, v2y);
                    fma2(o2[j][2], p2, v2z);
                    fma2(o2[j][3], p2, v2w);
                }
            }
        }
    }

    // epilogue: unpack, normalize, bf16 hi/lo store
    #pragma unroll
    for (int j = 0; j < 4; j++) {
        float oa[4], ob[4];
        #pragma unroll
        for (int c = 0; c < 4; c++) unpk2(o2[j][c], oa[c], ob[c]);
        #pragma unroll
        for (int half = 0; half < 2; half++) {
            int qi = 2 * j + half;
            const float* ov = half ? ob : oa;
            float inv = 1.f / l[qi];
            uint32_t hb[4], lb[4];
            #pragma unroll
            for (int c = 0; c < 4; c++) {
                float val = ov[c] * inv;
                hb[c] = f2bf_bits(val);
                lb[c] = f2bf_bits(val - bf2f(hb[c]));
            }
            size_t base = (size_t)(b * SEQ + q0 + qi) * 2048 + h * 128 + lane * 4;
            *reinterpret_cast<uint2*>(Ohi + base) =
                make_uint2(hb[0] | (hb[1] << 16), hb[2] | (hb[3] << 16));
            *reinterpret_cast<uint2*>(Olo + base) =
                make_uint2(lb[0] | (lb[1] << 16), lb[2] | (lb[3] << 16));
        }
    }
}

// ---------------- silu(gate)*up from fused gu, write bf16 hi/lo ----------------
__global__ void silu_mul_split(const float* __restrict__ gu, __nv_bfloat16* __restrict__ hi,
                               __nv_bfloat16* __restrict__ lo) {
    int idx = blockIdx.x * blockDim.x + threadIdx.x;
    if (idx >= T_TOK * 1408) return;
    int row = idx / 1408;
    int c4 = (idx - row * 1408) << 2;
    float4 g = *reinterpret_cast<const float4*>(gu + (size_t)row * 11264 + c4);
    float4 u = *reinterpret_cast<const float4*>(gu + (size_t)row * 11264 + 5632 + c4);
    float vals[4] = {
        (g.x / (1.f + __expf(-g.x))) * u.x,
        (g.y / (1.f + __expf(-g.y))) * u.y,
        (g.z / (1.f + __expf(-g.z))) * u.z,
        (g.w / (1.f + __expf(-g.w))) * u.w };
    uint32_t hb[4], lb[4];
    #pragma unroll
    for (int j = 0; j < 4; j++) {
        hb[j] = f2bf_bits(vals[j]);
        lb[j] = f2bf_bits(vals[j] - bf2f(hb[j]));
    }
    size_t base = (size_t)row * 5632 + c4;
    *reinterpret_cast<uint2*>(hi + base) = make_uint2(hb[0] | (hb[1] << 16), hb[2] | (hb[3] << 16));
    *reinterpret_cast<uint2*>(lo + base) = make_uint2(lb[0] | (lb[1] << 16), lb[2] | (lb[3] << 16));
}

// ---------------- orchestration ----------------
extern "C" void kernel_launch(void* const* d_in, const int* in_sizes, int n_in,
                              void* d_out, int out_size) {
    (void)in_sizes; (void)n_in; (void)out_size;
    const float* x       = (const float*)d_in[0];
    const int*   wq_q    = (const int*)  d_in[1];
    const float* wq_s    = (const float*)d_in[2];
    const float* bq      = (const float*)d_in[3];
    const int*   wk_q    = (const int*)  d_in[4];
    const float* wk_s    = (const float*)d_in[5];
    const float* bk      = (const float*)d_in[6];
    const int*   wv_q    = (const int*)  d_in[7];
    const float* wv_s    = (const float*)d_in[8];
    const float* bv      = (const float*)d_in[9];
    const int*   wo_q    = (const int*)  d_in[10];
    const float* wo_s    = (const float*)d_in[11];
    const int*   gate_q  = (const int*)  d_in[12];
    const float* gate_s  = (const float*)d_in[13];
    const int*   up_q    = (const int*)  d_in[14];
    const float* up_s    = (const float*)d_in[15];
    const int*   down_q  = (const int*)  d_in[16];
    const float* down_s  = (const float*)d_in[17];
    const float* w_in_ln = (const float*)d_in[18];
    const float* w_post_ln = (const float*)d_in[19];
    const int*   offset  = (const int*)  d_in[20];
    float* out = (float*)d_out;

    float *qkv, *x1, *gu, *scales, *biasb;
    __nv_bfloat16 *wbf, *ahi, *alo;
    cudaGetSymbolAddress((void**)&qkv,  g_qkv);
    cudaGetSymbolAddress((void**)&x1,   g_x1);
    cudaGetSymbolAddress((void**)&gu,   g_gu);
    cudaGetSymbolAddress((void**)&wbf,  g_wbf);
    cudaGetSymbolAddress((void**)&ahi,  g_ahi);
    cudaGetSymbolAddress((void**)&alo,  g_alo);
    cudaGetSymbolAddress((void**)&scales, g_scales);
    cudaGetSymbolAddress((void**)&biasb,  g_bias);

    cudaFuncSetAttribute(gemm_mma, cudaFuncAttributeMaxDynamicSharedMemorySize, GSMEM_BYTES);
    cudaFuncSetAttribute(attn_tiled, cudaFuncAttributeMaxDynamicSharedMemorySize, ASMEM_BYTES);

    // scale concat (D2D async copies, graph-safe)
    cudaMemcpyAsync(scales,          wq_s,   65536  * 4, cudaMemcpyDeviceToDevice);
    cudaMemcpyAsync(scales + 65536,  wk_s,   16384  * 4, cudaMemcpyDeviceToDevice);
    cudaMemcpyAsync(scales + 81920,  wv_s,   16384  * 4, cudaMemcpyDeviceToDevice);
    cudaMemcpyAsync(scales + 98304,  gate_s, 180224 * 4, cudaMemcpyDeviceToDevice);
    cudaMemcpyAsync(scales + 278528, up_s,   180224 * 4, cudaMemcpyDeviceToDevice);

    // kernel #1: all weights -> bf16
    w2bf_all<<<(W_TOTAL / 4 + 255) / 256, 256>>>(wq_q, wk_q, wv_q, wo_q, gate_q, up_q, down_q, wbf);

    // kernel #2: input rmsnorm + split
    rmsnorm_split<<<T_TOK, 256>>>(x, w_in_ln, ahi, alo);

    // kernel #3: bias concat (spacer so gemm stays in ncu's capture slot)
    bias_concat<<<12, 256>>>(bq, bk, bv, biasb);

    // kernel #4: fused qkv projection  (ncu captures this)
    gemm_mma<<<dim3(3072 / 128, T_TOK / 128), 512, GSMEM_BYTES>>>(
        ahi, alo, wbf + OFF_QKV, scales, biasb, nullptr, qkv, 3072, D_MODEL);

    // #5: fused RoPE
    rope_all<<<(T_TOK * 20 * 64 + 255) / 256, 256>>>(qkv, offset);

    // #6: attention -> ahi/alo
    attn_tiled<<<dim3(SEQ / 64, NHEAD, 2), 256, ASMEM_BYTES>>>(qkv, ahi, alo);

    // #7: o-projection + residual -> x1
    gemm_mma<<<dim3(D_MODEL / 128, T_TOK / 128), 512, GSMEM_BYTES>>>(
        ahi, alo, wbf + OFF_WO, wo_s, nullptr, x, x1, D_MODEL, D_MODEL);

    // #8: post rmsnorm + split
    rmsnorm_split<<<T_TOK, 256>>>(x1, w_post_ln, ahi, alo);

    // #9: fused gate|up projection
    gemm_mma<<<dim3(11264 / 128, T_TOK / 128), 512, GSMEM_BYTES>>>(
        ahi, alo, wbf + OFF_GU, scales + 98304, nullptr, nullptr, gu, 11264, D_MODEL);

    // #10: silu(gate)*up + split
    silu_mul_split<<<(T_TOK * 1408 + 255) / 256, 256>>>(gu, ahi, alo);

    // #11: down projection + residual -> out
    gemm_mma<<<dim3(D_MODEL / 128, T_TOK / 128), 512, GSMEM_BYTES>>>(
        ahi, alo, wbf + OFF_DOWN, down_s, nullptr, x1, out, D_MODEL, D_FF);
}

// round 11
// speedup vs baseline: 2.1945x; 1.0347x over previous
#include <cuda_runtime.h>
#include <cuda_bf16.h>
#include <cstdint>

#define T_TOK 2048
#define D_MODEL 2048
#define D_FF 5632
#define KV_DIM 512
#define SEQ 1024
#define NHEAD 16
#define NKV 4
#define HDIM 128

// ---------------- scratch (static device globals; no allocation) ----------------
__device__ float g_qkv[T_TOK * 3072];     // fused q|k|v rows
__device__ float g_x1 [T_TOK * D_MODEL];
__device__ float g_gu [T_TOK * 11264];    // fused gate|up
__device__ __nv_bfloat16 g_ahi[T_TOK * D_FF];
__device__ __nv_bfloat16 g_alo[T_TOK * D_FF];

// bf16 weights (int8 values EXACT in bf16; group scales applied in GEMM)
#define W_TOTAL 45088768
#define OFF_QKV  0            // 3072 x 2048  (wq | wk | wv rows)
#define OFF_WO   6291456      // 2048 x 2048
#define OFF_GU   10485760     // 11264 x 2048 (gate | up rows)
#define OFF_DOWN 33554432     // 2048 x 5632
__device__ __nv_bfloat16 g_wbf[W_TOTAL];
__device__ float g_scales[458752];        // qkv scales @0, gu scales @98304
__device__ float g_bias[3072];            // bq|bk|bv

typedef unsigned long long u64;

// ---------------- helpers ----------------
__device__ __forceinline__ uint32_t smem_u32(const void* p) {
    uint32_t a;
    asm("{ .reg .u64 t; cvta.to.shared.u64 t, %1; cvt.u32.u64 %0, t; }" : "=r"(a) : "l"(p));
    return a;
}
__device__ __forceinline__ uint32_t sw128(uint32_t off) { return off ^ ((off >> 3) & 0x70u); }
__device__ __forceinline__ uint32_t f2bf_bits(float f) {
    uint32_t u = __float_as_uint(f);
    return (u + 0x7fffu + ((u >> 16) & 1u)) >> 16;
}
__device__ __forceinline__ float bf2f(uint32_t b) { return __uint_as_float(b << 16); }

__device__ __forceinline__ u64 pk2(float x, float y) {
    u64 r;
    asm("mov.b64 %0, {%1, %2};" : "=l"(r) : "f"(x), "f"(y));
    return r;
}
__device__ __forceinline__ void fma2(u64& d, u64 a, u64 b) {
    asm("fma.rn.f32x2 %0, %1, %2, %0;" : "+l"(d) : "l"(a), "l"(b));
}
__device__ __forceinline__ void mul2(u64& d, u64 a) {
    asm("mul.rn.f32x2 %0, %0, %1;" : "+l"(d) : "l"(a));
}
__device__ __forceinline__ void unpk2(u64 v, float& lo, float& hi) {
    asm("mov.b64 {%0, %1}, %2;" : "=f"(lo), "=f"(hi) : "l"(v));
}

#define CP16(saddr, gptr) \
    asm volatile("cp.async.cg.shared.global [%0], [%1], 16;" :: "r"(saddr), "l"(gptr))
#define CP4(saddr, gptr) \
    asm volatile("cp.async.ca.shared.global [%0], [%1], 4;" :: "r"(saddr), "l"(gptr))
#define CP_COMMIT() asm volatile("cp.async.commit_group;" ::: "memory")
#define CP_WAIT(n)  asm volatile("cp.async.wait_group %0;" :: "n"(n) : "memory")

#define LDSM_X4(r, addr) \
    asm volatile("ldmatrix.sync.aligned.m8n8.x4.shared.b16 {%0,%1,%2,%3}, [%4];" \
        : "=r"((r)[0]), "=r"((r)[1]), "=r"((r)[2]), "=r"((r)[3]) : "r"(addr))

__device__ __forceinline__ void mma_bf16(float* c, const uint32_t* a, uint32_t b0, uint32_t b1) {
    asm volatile("mma.sync.aligned.m16n8k16.row.col.f32.bf16.bf16.f32 "
        "{%0,%1,%2,%3}, {%4,%5,%6,%7}, {%8,%9}, {%0,%1,%2,%3};"
        : "+f"(c[0]), "+f"(c[1]), "+f"(c[2]), "+f"(c[3])
        : "r"(a[0]), "r"(a[1]), "r"(a[2]), "r"(a[3]), "r"(b0), "r"(b1));
}

// ---------------- fused weight convert (all 7 weights, one launch) ----------------
__global__ void w2bf_all(const int* __restrict__ wq, const int* __restrict__ wk,
                         const int* __restrict__ wv, const int* __restrict__ wo,
                         const int* __restrict__ wg, const int* __restrict__ wu,
                         const int* __restrict__ wd, __nv_bfloat16* __restrict__ w) {
    int idx = blockIdx.x * blockDim.x + threadIdx.x;   // 4-vector index
    if (idx >= W_TOTAL / 4) return;
    const int* src;
    if      (idx < 1048576) src = wq + idx * 4;
    else if (idx < 1310720) src = wk + (idx - 1048576) * 4;
    else if (idx < 1572864) src = wv + (idx - 1310720) * 4;
    else if (idx < 2621440) src = wo + (idx - 1572864) * 4;
    else if (idx < 5505024) src = wg + (idx - 2621440) * 4;
    else if (idx < 8388608) src = wu + (idx - 5505024) * 4;
    else                    src = wd + (idx - 8388608) * 4;
    int4 v = *reinterpret_cast<const int4*>(src);
    uint32_t b0 = f2bf_bits((float)v.x), b1 = f2bf_bits((float)v.y);
    uint32_t b2 = f2bf_bits((float)v.z), b3 = f2bf_bits((float)v.w);
    *reinterpret_cast<uint2*>(w + (size_t)idx * 4) = make_uint2(b0 | (b1 << 16), b2 | (b3 << 16));
}

// ---------------- bias concat (also ncu launch-slot spacer) ----------------
__global__ void bias_concat(const float* __restrict__ bq, const float* __restrict__ bk,
                            const float* __restrict__ bv, float* __restrict__ dst) {
    int i = blockIdx.x * blockDim.x + threadIdx.x;
    if (i < 2048) dst[i] = bq[i];
    else if (i < 2560) dst[i] = bk[i - 2048];
    else if (i < 3072) dst[i] = bv[i - 2560];
}

// ---------------- RMSNorm fused with hi/lo split ----------------
__global__ void rmsnorm_split(const float* __restrict__ x, const float* __restrict__ w,
                              __nv_bfloat16* __restrict__ hi, __nv_bfloat16* __restrict__ lo) {
    int row = blockIdx.x, tid = threadIdx.x;
    const float4* xr = reinterpret_cast<const float4*>(x + (size_t)row * D_MODEL);
    const float4* wr = reinterpret_cast<const float4*>(w);

    float4 v0 = xr[tid], v1 = xr[tid + 256];
    float s = v0.x*v0.x + v0.y*v0.y + v0.z*v0.z + v0.w*v0.w
            + v1.x*v1.x + v1.y*v1.y + v1.z*v1.z + v1.w*v1.w;
    #pragma unroll
    for (int off = 16; off; off >>= 1) s += __shfl_xor_sync(0xffffffffu, s, off);
    __shared__ float red[8];
    if ((tid & 31) == 0) red[tid >> 5] = s;
    __syncthreads();
    float tot = 0.f;
    #pragma unroll
    for (int i = 0; i < 8; i++) tot += red[i];
    float inv = rsqrtf(tot * (1.0f / D_MODEL) + 1e-6f);

    float4 w0 = wr[tid], w1 = wr[tid + 256];
    float vals[8] = { v0.x*inv*w0.x, v0.y*inv*w0.y, v0.z*inv*w0.z, v0.w*inv*w0.w,
                      v1.x*inv*w1.x, v1.y*inv*w1.y, v1.z*inv*w1.z, v1.w*inv*w1.w };
    uint32_t hb[8], lb[8];
    #pragma unroll
    for (int i = 0; i < 8; i++) {
        hb[i] = f2bf_bits(vals[i]);
        lb[i] = f2bf_bits(vals[i] - bf2f(hb[i]));
    }
    uint2* hp = reinterpret_cast<uint2*>(hi + (size_t)row * D_MODEL);
    uint2* lp = reinterpret_cast<uint2*>(lo + (size_t)row * D_MODEL);
    hp[tid]       = make_uint2(hb[0] | (hb[1] << 16), hb[2] | (hb[3] << 16));
    hp[tid + 256] = make_uint2(hb[4] | (hb[5] << 16), hb[6] | (hb[7] << 16));
    lp[tid]       = make_uint2(lb[0] | (lb[1] << 16), lb[2] | (lb[3] << 16));
    lp[tid + 256] = make_uint2(lb[4] | (lb[5] << 16), lb[6] | (lb[7] << 16));
}

// ---------------- tensor-core GEMM via mma.sync, 4-stage cp.async ring (best known) ----------------
#define NSTAGE 4
#define STAGE_BYTES 49664
#define S_AHI 0
#define S_ALO 16384
#define S_W   32768
#define S_SC  49152
#define GSMEM_BYTES (NSTAGE * STAGE_BYTES + 1024)

__global__ void __launch_bounds__(512, 1)
gemm_mma(const __nv_bfloat16* __restrict__ Ahi, const __nv_bfloat16* __restrict__ Alo,
         const __nv_bfloat16* __restrict__ W, const float* __restrict__ Ws,
         const float* __restrict__ bias, const float* __restrict__ res,
         float* __restrict__ C, int O, int K) {
    extern __shared__ char dsm[];
    uint32_t sbraw = smem_u32(dsm);
    uint32_t sb = (sbraw + 1023u) & ~1023u;
    char* bp = dsm + (sb - sbraw);

    int tid = threadIdx.x, lane = tid & 31, wid = tid >> 5;
    int wm = wid >> 2, wn = wid & 3;
    int mb = blockIdx.y * 128, nb = blockIdx.x * 128;
    int nc = K >> 6;

    float acc[2][4][4];
    #pragma unroll
    for (int a = 0; a < 2; a++)
        #pragma unroll
        for (int b = 0; b < 4; b++)
            #pragma unroll
            for (int d = 0; d < 4; d++) acc[a][b][d] = 0.f;

    // prologue: stages 0..2
    #pragma unroll
    for (int pc = 0; pc < NSTAGE - 1; pc++) {
        uint32_t ss = sb + (uint32_t)pc * STAGE_BYTES;
        int k0 = pc << 6;
        #pragma unroll
        for (int it = 0; it < 2; it++) {
            int v = tid + it * 512;
            int row = v >> 3, kc = (v & 7) << 3;
            uint32_t so = sw128((uint32_t)(row * 128 + kc * 2));
            CP16(ss + S_AHI + so, Ahi + (size_t)(mb + row) * K + k0 + kc);
            CP16(ss + S_ALO + so, Alo + (size_t)(mb + row) * K + k0 + kc);
            CP16(ss + S_W + so,   W   + (size_t)(nb + row) * K + k0 + kc);
        }
        if (tid < 128) CP4(ss + S_SC + tid * 4, Ws + (size_t)(nb + tid) * nc + pc);
        CP_COMMIT();
    }

    int stage = 0;
    for (int c = 0; c < nc; c++) {
        int rem = nc - 1 - c;
        if (rem >= 2) { CP_WAIT(2); }
        else if (rem == 1) { CP_WAIT(1); }
        else { CP_WAIT(0); }
        __syncthreads();

        if (c + NSTAGE - 1 < nc) {
            int snum = stage + NSTAGE - 1; if (snum >= NSTAGE) snum -= NSTAGE;
            uint32_t ss = sb + (uint32_t)snum * STAGE_BYTES;
            int k0 = (c + NSTAGE - 1) << 6;
            #pragma unroll
            for (int it = 0; it < 2; it++) {
                int v = tid + it * 512;
                int row = v >> 3, kc = (v & 7) << 3;
                uint32_t so = sw128((uint32_t)(row * 128 + kc * 2));
                CP16(ss + S_AHI + so, Ahi + (size_t)(mb + row) * K + k0 + kc);
                CP16(ss + S_ALO + so, Alo + (size_t)(mb + row) * K + k0 + kc);
                CP16(ss + S_W + so,   W   + (size_t)(nb + row) * K + k0 + kc);
            }
            if (tid < 128) CP4(ss + S_SC + tid * 4, Ws + (size_t)(nb + tid) * nc + (c + NSTAGE - 1));
            CP_COMMIT();
        }

        uint32_t scur = sb + (uint32_t)stage * STAGE_BYTES;
        float gacc[2][4][4];
        #pragma unroll
        for (int a = 0; a < 2; a++)
            #pragma unroll
            for (int b = 0; b < 4; b++)
                #pragma unroll
                for (int d = 0; d < 4; d++) gacc[a][b][d] = 0.f;

        #pragma unroll
        for (int ks = 0; ks < 4; ks++) {
            int kh = ks << 4;
            uint32_t ah[2][4], al[2][4], bfr[2][4];
            #pragma unroll
            for (int mf = 0; mf < 2; mf++) {
                int row = wm * 32 + mf * 16 + (lane & 7) + ((lane >> 3) & 1) * 8;
                int kk = kh + ((lane >> 4) << 3);
                uint32_t so = sw128((uint32_t)(row * 128 + kk * 2));
                LDSM_X4(ah[mf], scur + S_AHI + so);
                LDSM_X4(al[mf], scur + S_ALO + so);
            }
            #pragma unroll
            for (int np = 0; np < 2; np++) {
                int n = wn * 32 + np * 16 + (lane & 7) + ((lane >> 4) << 3);
                int kk = kh + ((lane >> 3) & 1) * 8;
                LDSM_X4(bfr[np], scur + S_W + sw128((uint32_t)(n * 128 + kk * 2)));
            }
            #pragma unroll
            for (int mf = 0; mf < 2; mf++)
                #pragma unroll
                for (int nf = 0; nf < 4; nf++) {
                    uint32_t b0 = bfr[nf >> 1][(nf & 1) * 2], b1 = bfr[nf >> 1][(nf & 1) * 2 + 1];
                    mma_bf16(gacc[mf][nf], ah[mf], b0, b1);
                    mma_bf16(gacc[mf][nf], al[mf], b0, b1);
                }
        }

        const float* sp = reinterpret_cast<const float*>(bp + stage * STAGE_BYTES + S_SC);
        #pragma unroll
        for (int nf = 0; nf < 4; nf++) {
            int cc = wn * 32 + nf * 8 + (lane & 3) * 2;
            float s0 = sp[cc], s1 = sp[cc + 1];
            #pragma unroll
            for (int mf = 0; mf < 2; mf++) {
                acc[mf][nf][0] += gacc[mf][nf][0] * s0;
                acc[mf][nf][1] += gacc[mf][nf][1] * s1;
                acc[mf][nf][2] += gacc[mf][nf][2] * s0;
                acc[mf][nf][3] += gacc[mf][nf][3] * s1;
            }
        }
        if (++stage == NSTAGE) stage = 0;
    }

    #pragma unroll
    for (int mf = 0; mf < 2; mf++) {
        int row = mb + wm * 32 + mf * 16 + (lane >> 2);
        #pragma unroll
        for (int nf = 0; nf < 4; nf++) {
            int col = nb + wn * 32 + nf * 8 + (lane & 3) * 2;
            float v0 = acc[mf][nf][0], v1 = acc[mf][nf][1];
            float v2 = acc[mf][nf][2], v3 = acc[mf][nf][3];
            if (bias) {
                float b0 = bias[col], b1 = bias[col + 1];
                v0 += b0; v1 += b1; v2 += b0; v3 += b1;
            }
            size_t o0 = (size_t)row * O + col;
            size_t o1 = (size_t)(row + 8) * O + col;
            if (res) {
                float2 r0 = *reinterpret_cast<const float2*>(res + o0);
                float2 r1 = *reinterpret_cast<const float2*>(res + o1);
                v0 += r0.x; v1 += r0.y; v2 += r1.x; v3 += r1.y;
            }
            *reinterpret_cast<float2*>(C + o0) = make_float2(v0, v1);
            *reinterpret_cast<float2*>(C + o1) = make_float2(v2, v3);
        }
    }
}

// ---------------- fused RoPE on q (16 heads) + k (4 heads) ----------------
__global__ void rope_all(float* __restrict__ X, const int* __restrict__ offp) {
    int idx = blockIdx.x * blockDim.x + threadIdx.x;
    int total = T_TOK * 20 * 64;
    if (idx >= total) return;
    int j = idx & 63;
    int rest = idx >> 6;
    int h = rest % 20;
    int t = rest / 20;
    int s = t & (SEQ - 1);
    int col = (h < 16) ? h * 128 : 2048 + (h - 16) * 128;
    float pos = (float)(s + *offp);
    float inv = exp2f(-(float)j * (2.0f / 128.0f) * 19.931568569324174f);
    float ang = pos * inv;
    float c, sn;
    sincosf(ang, &sn, &c);
    float* p = X + (size_t)t * 3072 + col + j;
    float x1 = p[0], x2 = p[64];
    p[0]  = x1 * c - x2 * sn;
    p[64] = x2 * c + x1 * sn;
}

// ---------------- flash attention: packed-f32x2 + smem p-broadcast PV ----------------
// smem floats: q2 packed [0,8192) | kT [8192,12288) | v [12288,16384) | p2 [16384,18432)
#define ASMEM_BYTES 73728

__global__ void __launch_bounds__(256)
attn_tiled(const float* __restrict__ qkv, __nv_bfloat16* __restrict__ Ohi,
           __nv_bfloat16* __restrict__ Olo) {
    extern __shared__ float asmf[];
    float* kT  = asmf + 8192;        // [128][32]
    float* v_s = asmf + 12288;       // [32][128]

    int tid = threadIdx.x, warp = tid >> 5, lane = tid & 31;
    int Qb = ((int)gridDim.x - 1 - (int)blockIdx.x) * 64;
    int h = blockIdx.y, b = blockIdx.z, kh = h >> 2;
    const float scale = 0.08838834764831843f;

    // load q scaled into pair-packed layout
    for (int i = tid; i < 2048; i += 256) {
        int row = i & 63, d4 = (i >> 6) << 2;
        float4 qf = *reinterpret_cast<const float4*>(
            qkv + (size_t)(b * SEQ + Qb + row) * 3072 + h * 128 + d4);
        float* dst = asmf + ((row >> 3) << 10) + ((row & 7) >> 1) * 2 + (row & 1);
        dst[(d4 + 0) * 8] = qf.x * scale;
        dst[(d4 + 1) * 8] = qf.y * scale;
        dst[(d4 + 2) * 8] = qf.z * scale;
        dst[(d4 + 3) * 8] = qf.w * scale;
    }
    const u64* q2w = reinterpret_cast<const u64*>(asmf + (warp << 10));  // [d*4 + j]
    u64* p2w = reinterpret_cast<u64*>(asmf + 16384) + (warp << 7);       // [key*4 + j]

    float m[8], l[8];
    u64 o2[4][4];
    #pragma unroll
    for (int i = 0; i < 8; i++) { m[i] = -1e30f; l[i] = 0.f; }
    #pragma unroll
    for (int j = 0; j < 4; j++)
        #pragma unroll
        for (int c = 0; c < 4; c++) o2[j][c] = 0ull;

    int q0 = Qb + warp * 8;
    int nt = (Qb >> 5) + 2;
    int key = tid & 31, dch = tid >> 5;

    // prefetch tile 0 K/V into registers
    float4 kr[4], vr[4];
    {
        const float* kg = qkv + (size_t)(b * SEQ + key) * 3072 + 2048 + kh * 128 + dch * 16;
        const float* vg = kg + 512;
        #pragma unroll
        for (int j = 0; j < 4; j++) {
            kr[j] = *reinterpret_cast<const float4*>(kg + j * 4);
            vr[j] = *reinterpret_cast<const float4*>(vg + j * 4);
        }
    }

    for (int t = 0; t < nt; t++) {
        int kbase = t << 5;
        __syncthreads();
        #pragma unroll
        for (int j = 0; j < 4; j++) {
            int d0 = dch * 16 + j * 4;
            kT[(d0 + 0) * 32 + key] = kr[j].x;
            kT[(d0 + 1) * 32 + key] = kr[j].y;
            kT[(d0 + 2) * 32 + key] = kr[j].z;
            kT[(d0 + 3) * 32 + key] = kr[j].w;
            *reinterpret_cast<float4*>(v_s + key * 128 + d0) = vr[j];
        }
        __syncthreads();

        if (t + 1 < nt) {
            const float* kg = qkv + (size_t)(b * SEQ + ((t + 1) << 5) + key) * 3072
                              + 2048 + kh * 128 + dch * 16;
            const float* vg = kg + 512;
            #pragma unroll
            for (int j = 0; j < 4; j++) {
                kr[j] = *reinterpret_cast<const float4*>(kg + j * 4);
                vr[j] = *reinterpret_cast<const float4*>(vg + j * 4);
            }
        }

        if (kbase <= q0 + 7) {
            // --- QK dot: packed over query pairs (explicit vector q loads) ---
            u64 s2[4] = {0ull, 0ull, 0ull, 0ull};
            #pragma unroll 2
            for (int d = 0; d < 128; d += 4) {
                #pragma unroll
                for (int dd = 0; dd < 4; dd++) {
                    float kv = kT[(d + dd) * 32 + lane];
                    u64 k2 = pk2(kv, kv);
                    ulonglong2 qa = *reinterpret_cast<const ulonglong2*>(q2w + (d + dd) * 4);
                    ulonglong2 qb = *reinterpret_cast<const ulonglong2*>(q2w + (d + dd) * 4 + 2);
                    fma2(s2[0], qa.x, k2);
                    fma2(s2[1], qa.y, k2);
                    fma2(s2[2], qb.x, k2);
                    fma2(s2[3], qb.y, k2);
                }
            }
            float s[8];
            #pragma unroll
            for (int j = 0; j < 4; j++) unpk2(s2[j], s[2 * j], s[2 * j + 1]);

            // --- online softmax (same order as before) ---
            int keyg = kbase + lane;
            float p[8], corr[8];
            #pragma unroll
            for (int qi = 0; qi < 8; qi++) {
                float sv = (keyg <= q0 + qi) ? s[qi] : -1e30f;
                float mx = sv;
                #pragma unroll
                for (int off = 16; off; off >>= 1)
                    mx = fmaxf(mx, __shfl_xor_sync(0xffffffffu, mx, off));
                float mn = fmaxf(m[qi], mx);
                corr[qi] = __expf(m[qi] - mn);
                m[qi] = mn;
                float pv = __expf(sv - mn);
                p[qi] = pv;
                float ps = pv;
                #pragma unroll
                for (int off = 16; off; off >>= 1)
                    ps += __shfl_xor_sync(0xffffffffu, ps, off);
                l[qi] = l[qi] * corr[qi] + ps;
            }
            #pragma unroll
            for (int j = 0; j < 4; j++) {
                u64 c2 = pk2(corr[2 * j], corr[2 * j + 1]);
                #pragma unroll
                for (int c = 0; c < 4; c++) mul2(o2[j][c], c2);
            }

            // --- publish packed p to smem (per-warp broadcast buffer) ---
            __syncwarp();
            {
                ulonglong2 pa, pb;
                pa.x = pk2(p[0], p[1]); pa.y = pk2(p[2], p[3]);
                pb.x = pk2(p[4], p[5]); pb.y = pk2(p[6], p[7]);
                *reinterpret_cast<ulonglong2*>(p2w + lane * 4)     = pa;
                *reinterpret_cast<ulonglong2*>(p2w + lane * 4 + 2) = pb;
            }
            __syncwarp();

            // --- PV accumulate: broadcast p via LDS.128 instead of shfl ---
            #pragma unroll 4
            for (int k = 0; k < 32; k++) {
                float4 vf = *reinterpret_cast<const float4*>(v_s + k * 128 + lane * 4);
                u64 v2x = pk2(vf.x, vf.x), v2y = pk2(vf.y, vf.y);
                u64 v2z = pk2(vf.z, vf.z), v2w = pk2(vf.w, vf.w);
                ulonglong2 pa = *reinterpret_cast<const ulonglong2*>(p2w + k * 4);
                ulonglong2 pb = *reinterpret_cast<const ulonglong2*>(p2w + k * 4 + 2);
                fma2(o2[0][0], pa.x, v2x); fma2(o2[0][1], pa.x, v2y);
                fma2(o2[0][2], pa.x, v2z); fma2(o2[0][3], pa.x, v2w);
                fma2(o2[1][0], pa.y, v2x); fma2(o2[1][1], pa.y, v2y);
                fma2(o2[1][2], pa.y, v2z); fma2(o2[1][3], pa.y, v2w);
                fma2(o2[2][0], pb.x, v2x); fma2(o2[2][1], pb.x, v2y);
                fma2(o2[2][2], pb.x, v2z); fma2(o2[2][3], pb.x, v2w);
                fma2(o2[3][0], pb.y, v2x); fma2(o2[3][1], pb.y, v2y);
                fma2(o2[3][2], pb.y, v2z); fma2(o2[3][3], pb.y, v2w);
            }
        }
    }

    // epilogue: unpack, normalize, bf16 hi/lo store
    #pragma unroll
    for (int j = 0; j < 4; j++) {
        float oa[4], ob[4];
        #pragma unroll
        for (int c = 0; c < 4; c++) unpk2(o2[j][c], oa[c], ob[c]);
        #pragma unroll
        for (int half = 0; half < 2; half++) {
            int qi = 2 * j + half;
            const float* ov = half ? ob : oa;
            float inv = 1.f / l[qi];
            uint32_t hb[4], lb[4];
            #pragma unroll
            for (int c = 0; c < 4; c++) {
                float val = ov[c] * inv;
                hb[c] = f2bf_bits(val);
                lb[c] = f2bf_bits(val - bf2f(hb[c]));
            }
            size_t base = (size_t)(b * SEQ + q0 + qi) * 2048 + h * 128 + lane * 4;
            *reinterpret_cast<uint2*>(Ohi + base) =
                make_uint2(hb[0] | (hb[1] << 16), hb[2] | (hb[3] << 16));
            *reinterpret_cast<uint2*>(Olo + base) =
                make_uint2(lb[0] | (lb[1] << 16), lb[2] | (lb[3] << 16));
        }
    }
}

// ---------------- silu(gate)*up from fused gu, write bf16 hi/lo ----------------
__global__ void silu_mul_split(const float* __restrict__ gu, __nv_bfloat16* __restrict__ hi,
                               __nv_bfloat16* __restrict__ lo) {
    int idx = blockIdx.x * blockDim.x + threadIdx.x;
    if (idx >= T_TOK * 1408) return;
    int row = idx / 1408;
    int c4 = (idx - row * 1408) << 2;
    float4 g = *reinterpret_cast<const float4*>(gu + (size_t)row * 11264 + c4);
    float4 u = *reinterpret_cast<const float4*>(gu + (size_t)row * 11264 + 5632 + c4);
    float vals[4] = {
        (g.x / (1.f + __expf(-g.x))) * u.x,
        (g.y / (1.f + __expf(-g.y))) * u.y,
        (g.z / (1.f + __expf(-g.z))) * u.z,
        (g.w / (1.f + __expf(-g.w))) * u.w };
    uint32_t hb[4], lb[4];
    #pragma unroll
    for (int j = 0; j < 4; j++) {
        hb[j] = f2bf_bits(vals[j]);
        lb[j] = f2bf_bits(vals[j] - bf2f(hb[j]));
    }
    size_t base = (size_t)row * 5632 + c4;
    *reinterpret_cast<uint2*>(hi + base) = make_uint2(hb[0] | (hb[1] << 16), hb[2] | (hb[3] << 16));
    *reinterpret_cast<uint2*>(lo + base) = make_uint2(lb[0] | (lb[1] << 16), lb[2] | (lb[3] << 16));
}

// ---------------- orchestration ----------------
extern "C" void kernel_launch(void* const* d_in, const int* in_sizes, int n_in,
                              void* d_out, int out_size) {
    (void)in_sizes; (void)n_in; (void)out_size;
    const float* x       = (const float*)d_in[0];
    const int*   wq_q    = (const int*)  d_in[1];
    const float* wq_s    = (const float*)d_in[2];
    const float* bq      = (const float*)d_in[3];
    const int*   wk_q    = (const int*)  d_in[4];
    const float* wk_s    = (const float*)d_in[5];
    const float* bk      = (const float*)d_in[6];
    const int*   wv_q    = (const int*)  d_in[7];
    const float* wv_s    = (const float*)d_in[8];
    const float* bv      = (const float*)d_in[9];
    const int*   wo_q    = (const int*)  d_in[10];
    const float* wo_s    = (const float*)d_in[11];
    const int*   gate_q  = (const int*)  d_in[12];
    const float* gate_s  = (const float*)d_in[13];
    const int*   up_q    = (const int*)  d_in[14];
    const float* up_s    = (const float*)d_in[15];
    const int*   down_q  = (const int*)  d_in[16];
    const float* down_s  = (const float*)d_in[17];
    const float* w_in_ln = (const float*)d_in[18];
    const float* w_post_ln = (const float*)d_in[19];
    const int*   offset  = (const int*)  d_in[20];
    float* out = (float*)d_out;

    float *qkv, *x1, *gu, *scales, *biasb;
    __nv_bfloat16 *wbf, *ahi, *alo;
    cudaGetSymbolAddress((void**)&qkv,  g_qkv);
    cudaGetSymbolAddress((void**)&x1,   g_x1);
    cudaGetSymbolAddress((void**)&gu,   g_gu);
    cudaGetSymbolAddress((void**)&wbf,  g_wbf);
    cudaGetSymbolAddress((void**)&ahi,  g_ahi);
    cudaGetSymbolAddress((void**)&alo,  g_alo);
    cudaGetSymbolAddress((void**)&scales, g_scales);
    cudaGetSymbolAddress((void**)&biasb,  g_bias);

    cudaFuncSetAttribute(gemm_mma, cudaFuncAttributeMaxDynamicSharedMemorySize, GSMEM_BYTES);
    cudaFuncSetAttribute(attn_tiled, cudaFuncAttributeMaxDynamicSharedMemorySize, ASMEM_BYTES);

    // scale concat (D2D async copies, graph-safe)
    cudaMemcpyAsync(scales,          wq_s,   65536  * 4, cudaMemcpyDeviceToDevice);
    cudaMemcpyAsync(scales + 65536,  wk_s,   16384  * 4, cudaMemcpyDeviceToDevice);
    cudaMemcpyAsync(scales + 81920,  wv_s,   16384  * 4, cudaMemcpyDeviceToDevice);
    cudaMemcpyAsync(scales + 98304,  gate_s, 180224 * 4, cudaMemcpyDeviceToDevice);
    cudaMemcpyAsync(scales + 278528, up_s,   180224 * 4, cudaMemcpyDeviceToDevice);

    // kernel #1: all weights -> bf16
    w2bf_all<<<(W_TOTAL / 4 + 255) / 256, 256>>>(wq_q, wk_q, wv_q, wo_q, gate_q, up_q, down_q, wbf);

    // kernel #2: input rmsnorm + split
    rmsnorm_split<<<T_TOK, 256>>>(x, w_in_ln, ahi, alo);

    // kernel #3: bias concat (spacer so gemm stays in ncu's capture slot)
    bias_concat<<<12, 256>>>(bq, bk, bv, biasb);

    // kernel #4: fused qkv projection  (ncu captures this)
    gemm_mma<<<dim3(3072 / 128, T_TOK / 128), 512, GSMEM_BYTES>>>(
        ahi, alo, wbf + OFF_QKV, scales, biasb, nullptr, qkv, 3072, D_MODEL);

    // #5: fused RoPE
    rope_all<<<(T_TOK * 20 * 64 + 255) / 256, 256>>>(qkv, offset);

    // #6: attention -> ahi/alo
    attn_tiled<<<dim3(SEQ / 64, NHEAD, 2), 256, ASMEM_BYTES>>>(qkv, ahi, alo);

    // #7: o-projection + residual -> x1
    gemm_mma<<<dim3(D_MODEL / 128, T_TOK / 128), 512, GSMEM_BYTES>>>(
        ahi, alo, wbf + OFF_WO, wo_s, nullptr, x, x1, D_MODEL, D_MODEL);

    // #8: post rmsnorm + split
    rmsnorm_split<<<T_TOK, 256>>>(x1, w_post_ln, ahi, alo);

    // #9: fused gate|up projection
    gemm_mma<<<dim3(11264 / 128, T_TOK / 128), 512, GSMEM_BYTES>>>(
        ahi, alo, wbf + OFF_GU, scales + 98304, nullptr, nullptr, gu, 11264, D_MODEL);

    // #10: silu(gate)*up + split
    silu_mul_split<<<(T_TOK * 1408 + 255) / 256, 256>>>(gu, ahi, alo);

    // #11: down projection + residual -> out
    gemm_mma<<<dim3(D_MODEL / 128, T_TOK / 128), 512, GSMEM_BYTES>>>(
        ahi, alo, wbf + OFF_DOWN, down_s, nullptr, x1, out, D_MODEL, D_FF);
}